// round 14
// baseline (speedup 1.0000x reference)
#include <cuda_runtime.h>
#include <cuda_fp16.h>
#include <cstdint>
#include <math.h>

// ---------------- problem constants ----------------
#define Vv 8192
#define Cc 512
#define Hh 16
#define HSs 32
#define Ll 12
#define FFf 2048
#define Bb 8
#define Tt 1024
#define BT (Bb*Tt)              // 8192
#define BTV ((size_t)BT * Vv)   // 67108864
#define NQKV 1536
#define LOSCALE 1024.f
#define INV_LOSCALE (1.f/1024.f)

typedef unsigned int u32;
typedef unsigned long long u64;

// ---------------- scratch (device globals, no allocation) ----------------
__device__ float  g_x   [BT*Cc];     // residual stream, fp32
__device__ __half g_qkvh[BT*NQKV];   // qkv hi
__device__ __half g_qkvl[BT*NQKV];   // qkv lo (UNscaled, attn input)
__device__ __half g_hh  [BT*Cc];
__device__ __half g_hl  [BT*Cc];     // scaled x1024
__device__ __half g_oh  [BT*Cc];
__device__ __half g_ol  [BT*Cc];     // scaled x1024
__device__ __half g_ffh [BT*FFf];
__device__ __half g_ffl [BT*FFf];    // scaled x1024
__device__ float  g_expsum[BT];
__device__ float  g_loss;

// split fp16 weights, [N][K]; lo arrays scaled x1024
__device__ __half g_wqkv_h[Ll*NQKV*Cc];
__device__ __half g_wqkv_l[Ll*NQKV*Cc];
__device__ __half g_wo_h  [Ll*Cc*Cc];
__device__ __half g_wo_l  [Ll*Cc*Cc];
__device__ __half g_w1_h  [Ll*FFf*Cc];
__device__ __half g_w1_l  [Ll*FFf*Cc];
__device__ __half g_w2_h  [Ll*Cc*FFf];
__device__ __half g_w2_l  [Ll*Cc*FFf];
__device__ __half g_wlm_h [Vv*Cc];
__device__ __half g_wlm_l [Vv*Cc];

// ---------------- asm wrappers ----------------
__device__ __forceinline__ void mma_f16(float* d, const u32* a, const u32* b) {
    asm volatile("mma.sync.aligned.m16n8k16.row.col.f32.f16.f16.f32 "
        "{%0,%1,%2,%3}, {%4,%5,%6,%7}, {%8,%9}, {%0,%1,%2,%3};"
        : "+f"(d[0]), "+f"(d[1]), "+f"(d[2]), "+f"(d[3])
        : "r"(a[0]), "r"(a[1]), "r"(a[2]), "r"(a[3]),
          "r"(b[0]), "r"(b[1]));
}
// fp16 accumulator variant (possible 2x rate)
__device__ __forceinline__ void mma_h16(u32* d, const u32* a, const u32* b) {
    asm volatile("mma.sync.aligned.m16n8k16.row.col.f16.f16.f16.f16 "
        "{%0,%1}, {%2,%3,%4,%5}, {%6,%7}, {%0,%1};"
        : "+r"(d[0]), "+r"(d[1])
        : "r"(a[0]), "r"(a[1]), "r"(a[2]), "r"(a[3]),
          "r"(b[0]), "r"(b[1]));
}
__device__ __forceinline__ void ldsm4(u32* r, u32 addr) {
    asm volatile("ldmatrix.sync.aligned.m8n8.x4.shared.b16 "
        "{%0,%1,%2,%3}, [%4];"
        : "=r"(r[0]), "=r"(r[1]), "=r"(r[2]), "=r"(r[3]) : "r"(addr));
}
__device__ __forceinline__ void ldsm4t(u32* r, u32 addr) {
    asm volatile("ldmatrix.sync.aligned.m8n8.x4.trans.shared.b16 "
        "{%0,%1,%2,%3}, [%4];"
        : "=r"(r[0]), "=r"(r[1]), "=r"(r[2]), "=r"(r[3]) : "r"(addr));
}
__device__ __forceinline__ void cpa16(u32 dst, const void* src) {
    asm volatile("cp.async.cg.shared.global [%0], [%1], 16;" :: "r"(dst), "l"(src));
}
__device__ __forceinline__ void cp_commit() {
    asm volatile("cp.async.commit_group;" ::: "memory");
}
template<int N>
__device__ __forceinline__ void cp_wait() {
    asm volatile("cp.async.wait_group %0;" :: "n"(N) : "memory");
}
__device__ __forceinline__ u32 packh2(float x, float y) {
    __half2 h = __halves2half2(__float2half_rn(x), __float2half_rn(y));
    return *(u32*)&h;
}

// ---------------- fused weight prep (lo scaled x1024) ----------------
__device__ __forceinline__ void tsplit_tile(const float* __restrict__ src,
                                            __half* __restrict__ hi,
                                            __half* __restrict__ lo,
                                            int K, int N, int n0, int k0,
                                            float (*t)[33], int tx, int ty) {
    #pragma unroll
    for (int r = 0; r < 4; r++)
        t[ty + 8*r][tx] = src[(size_t)(k0 + ty + 8*r) * N + n0 + tx];
    __syncthreads();
    #pragma unroll
    for (int r = 0; r < 4; r++) {
        int n = ty + 8*r;
        float v = t[tx][n];
        __half vh = __float2half_rn(v);
        __half vl = __float2half_rn((v - __half2float(vh)) * LOSCALE);
        size_t o = (size_t)(n0 + n) * K + k0 + tx;
        hi[o] = vh; lo[o] = vl;
    }
}

__global__ __launch_bounds__(256) void prep_k(const float* __restrict__ Wq,
                                              const float* __restrict__ Wk,
                                              const float* __restrict__ Wv,
                                              const float* __restrict__ Wo,
                                              const float* __restrict__ W1,
                                              const float* __restrict__ W2,
                                              const float* __restrict__ Wlm) {
    __shared__ float t[32][33];
    int b = blockIdx.x;
    int tx = threadIdx.x, ty = threadIdx.y;
    if (b < 3072) {
        int c0 = (b & 15) * 32, h = (b >> 4) & 15, l = b >> 8;
        const float* srcs[3] = {Wq, Wk, Wv};
        for (int s = 0; s < 3; s++) {
            const float* src = srcs[s] + ((size_t)(l*Hh + h) * Cc) * HSs;
            #pragma unroll
            for (int r = 0; r < 4; r++)
                t[ty + 8*r][tx] = src[(size_t)(c0 + ty + 8*r) * HSs + tx];
            __syncthreads();
            size_t nbase = (size_t)l * NQKV + s * 512 + h * 32;
            #pragma unroll
            for (int r = 0; r < 4; r++) {
                int d = ty + 8*r;
                float v = t[tx][d];
                __half hi = __float2half_rn(v);
                __half lo = __float2half_rn((v - __half2float(hi)) * LOSCALE);
                size_t o = (nbase + d) * Cc + c0 + tx;
                g_wqkv_h[o] = hi; g_wqkv_l[o] = lo;
            }
            __syncthreads();
        }
    } else if (b < 6144) {
        b -= 3072;
        int l = b >> 8, n0 = (b & 15) * 32, k0 = ((b >> 4) & 15) * 32;
        tsplit_tile(Wo + (size_t)l*Cc*Cc, g_wo_h + (size_t)l*Cc*Cc, g_wo_l + (size_t)l*Cc*Cc,
                    Cc, Cc, n0, k0, t, tx, ty);
    } else if (b < 18432) {
        b -= 6144;
        int l = b >> 10, rem = b & 1023;
        int n0 = (rem & 63) * 32, k0 = (rem >> 6) * 32;
        tsplit_tile(W1 + (size_t)l*Cc*FFf, g_w1_h + (size_t)l*FFf*Cc, g_w1_l + (size_t)l*FFf*Cc,
                    Cc, FFf, n0, k0, t, tx, ty);
    } else if (b < 30720) {
        b -= 18432;
        int l = b >> 10, rem = b & 1023;
        int n0 = (rem & 15) * 32, k0 = (rem >> 4) * 32;
        tsplit_tile(W2 + (size_t)l*FFf*Cc, g_w2_h + (size_t)l*Cc*FFf, g_w2_l + (size_t)l*Cc*FFf,
                    FFf, Cc, n0, k0, t, tx, ty);
    } else {
        b -= 30720;
        int n0 = (b & 255) * 32, k0 = (b >> 8) * 32;
        tsplit_tile(Wlm, g_wlm_h, g_wlm_l, Cc, Vv, n0, k0, t, tx, ty);
    }
}

// ---------------- embedding ----------------
__global__ __launch_bounds__(128) void embed_k(const int* __restrict__ idx,
                                               const int* __restrict__ lab,
                                               const float* __restrict__ tok_emb,
                                               const float* __restrict__ lab_emb,
                                               const float* __restrict__ pos_emb) {
    int i = blockIdx.x;
    int t = i & (Tt-1);
    int ix = idx[i];
    int lb = lab[i];
    const float4* te = (const float4*)(tok_emb + (size_t)ix*Cc);
    const float4* le = (const float4*)(lab_emb + (size_t)lb*Cc);
    const float4* pe = (const float4*)(pos_emb + (size_t)t *Cc);
    float4* xo = (float4*)(g_x + (size_t)i*Cc);
    int c = threadIdx.x;
    float4 a = te[c], b = le[c], p = pe[c];
    xo[c] = make_float4(a.x+b.x+p.x, a.y+b.y+p.y, a.z+b.z+p.z, a.w+b.w+p.w);
}

// ---------------- layernorm: fp32 in -> fp16 hi + scaled lo ----------------
__global__ __launch_bounds__(128) void lnorm_k(const float* __restrict__ x,
                                               const float* __restrict__ g,
                                               const float* __restrict__ b,
                                               __half* __restrict__ yh,
                                               __half* __restrict__ yl) {
    int row = blockIdx.x;
    const float4* xr = (const float4*)(x + (size_t)row*Cc);
    float4 v = xr[threadIdx.x];
    float s  = v.x+v.y+v.z+v.w;
    float s2 = v.x*v.x + v.y*v.y + v.z*v.z + v.w*v.w;
    for (int o = 16; o > 0; o >>= 1) {
        s  += __shfl_down_sync(0xffffffff, s,  o);
        s2 += __shfl_down_sync(0xffffffff, s2, o);
    }
    __shared__ float sh[4], sh2[4];
    int wid = threadIdx.x >> 5, lane = threadIdx.x & 31;
    if (lane == 0) { sh[wid] = s; sh2[wid] = s2; }
    __syncthreads();
    __shared__ float smean, srstd;
    if (threadIdx.x == 0) {
        float ts = sh[0]+sh[1]+sh[2]+sh[3];
        float ts2 = sh2[0]+sh2[1]+sh2[2]+sh2[3];
        float mean = ts * (1.0f/Cc);
        float var = ts2 * (1.0f/Cc) - mean*mean;
        smean = mean;
        srstd = rsqrtf(var + 1e-5f);
    }
    __syncthreads();
    float mean = smean, rstd = srstd;
    int c = threadIdx.x * 4;
    float4 gg = *(const float4*)(g + c);
    float4 bb = *(const float4*)(b + c);
    float ov[4];
    ov[0] = (v.x-mean)*rstd*gg.x + bb.x;
    ov[1] = (v.y-mean)*rstd*gg.y + bb.y;
    ov[2] = (v.z-mean)*rstd*gg.z + bb.z;
    ov[3] = (v.w-mean)*rstd*gg.w + bb.w;
    __half hv[4], lv[4];
    #pragma unroll
    for (int e = 0; e < 4; e++) {
        hv[e] = __float2half_rn(ov[e]);
        lv[e] = __float2half_rn((ov[e] - __half2float(hv[e])) * LOSCALE);
    }
    *(uint2*)(yh + (size_t)row*Cc + c) = *(uint2*)hv;
    *(uint2*)(yl + (size_t)row*Cc + c) = *(uint2*)lv;
}

// ---------------- GEMM: fp16x3, corrections in fp16-acc MMA ----------------
// main: Ah*Bh in f32 acc; corrections Al'*Bh + Ah*Bl' in f16 acc (x1024 scaled lo);
// epilogue: v = acc + corr/1024.
#define SAL_B 10240
#define SBH_B 20480
#define SBL_B 30720
#define STG_B 40960
#define TG_SMEM (2*STG_B)

template<bool BIAS, bool RELU, bool RES, bool SPLIT, bool EXPS, bool LOSC>
__global__ __launch_bounds__(256) void tgemm_k(const __half* __restrict__ Ahg,
                                               const __half* __restrict__ Alg,
                                               const __half* __restrict__ Bhg,
                                               const __half* __restrict__ Blg,
                                               const float* __restrict__ bias,
                                               const float* __restrict__ res,
                                               float* __restrict__ Cf,
                                               __half* __restrict__ Ch,
                                               __half* __restrict__ Cl,
                                               float* __restrict__ expsum,
                                               int M, int N, int K) {
    extern __shared__ __half smd[];
    const int tid = threadIdx.x;
    const int lane = tid & 31, w = tid >> 5;
    const int row0 = blockIdx.y * 128, col0 = blockIdx.x * 128;
    const int m0w = (w >> 2) * 64, n0w = (w & 3) * 32;
    const u32 sb = (u32)__cvta_generic_to_shared(smd);

    float acc[4][4][4];
    u32 cacc[4][4][2];
    #pragma unroll
    for (int i = 0; i < 4; i++)
        #pragma unroll
        for (int j = 0; j < 4; j++) {
            #pragma unroll
            for (int e = 0; e < 4; e++) acc[i][j][e] = 0.f;
            cacc[i][j][0] = 0u; cacc[i][j][1] = 0u;
        }

    const int nk = K >> 5;
    const int r = tid >> 1;
    const int hofs = (tid & 1) << 4;
    const __half* aHp = Ahg + (size_t)(row0 + r) * K + hofs;
    const __half* aLp = Alg + (size_t)(row0 + r) * K + hofs;
    const __half* bHp = Bhg + (size_t)(col0 + r) * K + hofs;
    const __half* bLp = Blg + (size_t)(col0 + r) * K + hofs;
    const u32 dstA = sb + (u32)(r * 80 + hofs * 2);

    #define TG_ISSUE(bufbyte, kc) do {                                   \
        int _ko = (kc) << 5;                                             \
        u32 _d = dstA + (bufbyte);                                       \
        cpa16(_d,                 aHp + _ko);                            \
        cpa16(_d + 16,            aHp + _ko + 8);                        \
        cpa16(_d + SAL_B,         aLp + _ko);                            \
        cpa16(_d + SAL_B + 16,    aLp + _ko + 8);                        \
        cpa16(_d + SBH_B,         bHp + _ko);                            \
        cpa16(_d + SBH_B + 16,    bHp + _ko + 8);                        \
        cpa16(_d + SBL_B,         bLp + _ko);                            \
        cpa16(_d + SBL_B + 16,    bLp + _ko + 8);                        \
    } while (0)

    TG_ISSUE(0, 0);
    cp_commit();

    const int lr = lane & 7, lg1 = (lane >> 3) & 1, lg2 = lane >> 4;

    for (int kt = 0; kt < nk; kt++) {
        const u32 cur = (u32)((kt & 1) * STG_B);
        cp_wait<0>();
        __syncthreads();
        if (kt + 1 < nk) {
            TG_ISSUE((u32)(((kt + 1) & 1) * STG_B), kt + 1);
            cp_commit();
        }

        #pragma unroll
        for (int ks = 0; ks < 32; ks += 16) {
            u32 afh[4][4], afl[4][4];
            #pragma unroll
            for (int mi = 0; mi < 4; mi++) {
                int row = m0w + mi*16 + lr + lg1*8;
                u32 ad = sb + cur + (u32)((row*40 + ks + lg2*8) * 2);
                ldsm4(afh[mi], ad);
                ldsm4(afl[mi], ad + SAL_B);
            }
            u32 bfh[4][2], bfl[4][2];
            #pragma unroll
            for (int bi = 0; bi < 2; bi++) {
                int n = n0w + bi*16 + lr + lg2*8;
                u32 bd = sb + cur + SBH_B + (u32)((n*40 + ks + lg1*8) * 2);
                u32 t1[4], t2[4];
                ldsm4(t1, bd);
                ldsm4(t2, bd + (SBL_B - SBH_B));
                bfh[2*bi][0]   = t1[0]; bfh[2*bi][1]   = t1[1];
                bfh[2*bi+1][0] = t1[2]; bfh[2*bi+1][1] = t1[3];
                bfl[2*bi][0]   = t2[0]; bfl[2*bi][1]   = t2[1];
                bfl[2*bi+1][0] = t2[2]; bfl[2*bi+1][1] = t2[3];
            }
            #pragma unroll
            for (int mi = 0; mi < 4; mi++)
                #pragma unroll
                for (int ni = 0; ni < 4; ni++) {
                    mma_f16(acc[mi][ni], afh[mi], bfh[ni]);   // main (f32 acc)
                    mma_h16(cacc[mi][ni], afl[mi], bfh[ni]);  // corr (f16 acc)
                    mma_h16(cacc[mi][ni], afh[mi], bfl[ni]);  // corr (f16 acc)
                }
        }
    }
    #undef TG_ISSUE

    #pragma unroll
    for (int mi = 0; mi < 4; mi++) {
        int r0 = row0 + m0w + mi*16 + (lane >> 2);
        float es0 = 0.f, es1 = 0.f;
        #pragma unroll
        for (int ni = 0; ni < 4; ni++) {
            int cc = col0 + n0w + ni*8 + (lane & 3)*2;
            float2 cf0 = __half22float2(*(__half2*)&cacc[mi][ni][0]);
            float2 cf1 = __half22float2(*(__half2*)&cacc[mi][ni][1]);
            float2 v0 = make_float2(acc[mi][ni][0] + cf0.x*INV_LOSCALE,
                                    acc[mi][ni][1] + cf0.y*INV_LOSCALE);
            float2 v1 = make_float2(acc[mi][ni][2] + cf1.x*INV_LOSCALE,
                                    acc[mi][ni][3] + cf1.y*INV_LOSCALE);
            if (BIAS) {
                float2 bb = *(const float2*)(bias + cc);
                v0.x += bb.x; v0.y += bb.y; v1.x += bb.x; v1.y += bb.y;
            }
            if (RELU) {
                v0.x = fmaxf(v0.x, 0.f); v0.y = fmaxf(v0.y, 0.f);
                v1.x = fmaxf(v1.x, 0.f); v1.y = fmaxf(v1.y, 0.f);
            }
            if (RES) {
                float2 ra = *(const float2*)(res + (size_t)r0*N + cc);
                float2 rb = *(const float2*)(res + (size_t)(r0+8)*N + cc);
                v0.x += ra.x; v0.y += ra.y; v1.x += rb.x; v1.y += rb.y;
            }
            if (SPLIT) {
                const float ls = LOSC ? LOSCALE : 1.f;
                __half h0 = __float2half_rn(v0.x), h1 = __float2half_rn(v0.y);
                __half h2 = __float2half_rn(v1.x), h3 = __float2half_rn(v1.y);
                __half l0 = __float2half_rn((v0.x - __half2float(h0)) * ls);
                __half l1 = __float2half_rn((v0.y - __half2float(h1)) * ls);
                __half l2 = __float2half_rn((v1.x - __half2float(h2)) * ls);
                __half l3 = __float2half_rn((v1.y - __half2float(h3)) * ls);
                *(__half2*)(Ch + (size_t)r0*N + cc)     = __halves2half2(h0, h1);
                *(__half2*)(Ch + (size_t)(r0+8)*N + cc) = __halves2half2(h2, h3);
                *(__half2*)(Cl + (size_t)r0*N + cc)     = __halves2half2(l0, l1);
                *(__half2*)(Cl + (size_t)(r0+8)*N + cc) = __halves2half2(l2, l3);
            } else {
                *(float2*)(Cf + (size_t)r0*N + cc) = v0;
                *(float2*)(Cf + (size_t)(r0+8)*N + cc) = v1;
            }
            if (EXPS) {
                es0 += __expf(v0.x) + __expf(v0.y);
                es1 += __expf(v1.x) + __expf(v1.y);
            }
        }
        if (EXPS) {
            es0 += __shfl_xor_sync(0xffffffffu, es0, 1);
            es0 += __shfl_xor_sync(0xffffffffu, es0, 2);
            es1 += __shfl_xor_sync(0xffffffffu, es1, 1);
            es1 += __shfl_xor_sync(0xffffffffu, es1, 2);
            if ((lane & 3) == 0) {
                atomicAdd(&expsum[r0], es0);
                atomicAdd(&expsum[r0 + 8], es1);
            }
        }
    }
}

// ---------------- tensor-core causal flash attention ----------------
// qkv lo inputs are UNscaled; ol output scaled x1024 (feeds wo GEMM).
#define AP 40
#define ASMEM (25600*2)

__global__ __launch_bounds__(128) void attn2_k(const __half* __restrict__ qkvh,
                                               const __half* __restrict__ qkvl,
                                               __half* __restrict__ ohg,
                                               __half* __restrict__ olg) {
    extern __shared__ __half ash[];
    const u32 sb = (u32)__cvta_generic_to_shared(ash);
    const int tid = threadIdx.x;
    const int l = tid & 31, w = tid >> 5;
    const int bh = blockIdx.y, b = bh >> 4, h = bh & 15;
    const int qt = (int)gridDim.x - 1 - (int)blockIdx.x;
    const float scale = 0.17677669529663689f;

    const int tb = b*Tt + qt*64;
    const int rr = tid >> 1;
    const int ss = tid & 1;

    {
        const __half* qh = qkvh + (size_t)(tb + rr)*NQKV + h*HSs + ss*16;
        const __half* ql = qkvl + (size_t)(tb + rr)*NQKV + h*HSs + ss*16;
        u32 d = sb + (u32)((rr*AP + ss*16) * 2);
        cpa16(d, qh);              cpa16(d + 16, qh + 8);
        cpa16(d + 2560*2, ql);     cpa16(d + 2560*2 + 16, ql + 8);
    }
    #define AT_ISSUE(stgh, kt) do {                                          \
        int _tok = b*Tt + (kt)*64 + rr;                                      \
        const __half* _kh = qkvh + (size_t)_tok*NQKV + 512  + h*HSs + ss*16; \
        const __half* _kl = qkvl + (size_t)_tok*NQKV + 512  + h*HSs + ss*16; \
        const __half* _vh = qkvh + (size_t)_tok*NQKV + 1024 + h*HSs + ss*16; \
        const __half* _vl = qkvl + (size_t)_tok*NQKV + 1024 + h*HSs + ss*16; \
        u32 _d = sb + (u32)(((stgh) + rr*AP + ss*16) * 2);                   \
        cpa16(_d, _kh);               cpa16(_d + 16, _kh + 8);               \
        cpa16(_d + 2560*2, _kl);      cpa16(_d + 2560*2 + 16, _kl + 8);      \
        cpa16(_d + 5120*2, _vh);      cpa16(_d + 5120*2 + 16, _vh + 8);      \
        cpa16(_d + 7680*2, _vl);      cpa16(_d + 7680*2 + 16, _vl + 8);      \
    } while (0)

    AT_ISSUE(5120, 0);
    cp_commit();

    const int lr = l & 7, lg1 = (l >> 3) & 1, lg2 = l >> 4;
    const int g = l >> 2;
    const int cq = (l & 3) * 2;

    u32 qah[2][4], qal[2][4];
    float m0 = -1e30f, m1 = -1e30f, sum0 = 0.f, sum1 = 0.f;
    float oacc[4][4];
    #pragma unroll
    for (int i = 0; i < 4; i++)
        #pragma unroll
        for (int e = 0; e < 4; e++) oacc[i][e] = 0.f;

    for (int kt = 0; kt <= qt; kt++) {
        const u32 stg = (u32)(5120 + (kt & 1) * 10240);
        cp_wait<0>();
        __syncthreads();
        if (kt < qt) { AT_ISSUE((u32)(5120 + ((kt+1) & 1) * 10240), kt + 1); cp_commit(); }
        if (kt == 0) {
            #pragma unroll
            for (int ks = 0; ks < 2; ks++) {
                int row = w*16 + lr + lg1*8;
                u32 ad = sb + (u32)((row*AP + ks*16 + lg2*8) * 2);
                ldsm4(qah[ks], ad);
                ldsm4(qal[ks], ad + 2560*2);
            }
        }

        float sc[8][4];
        #pragma unroll
        for (int nt = 0; nt < 8; nt++)
            #pragma unroll
            for (int e = 0; e < 4; e++) sc[nt][e] = 0.f;

        #pragma unroll
        for (int ks = 0; ks < 2; ks++) {
            u32 kbh[8][2], kbl[8][2];
            #pragma unroll
            for (int bi = 0; bi < 4; bi++) {
                int n = bi*16 + lr + lg2*8;
                u32 bd = sb + (u32)((stg + n*AP + ks*16 + lg1*8) * 2);
                u32 t1[4], t2[4];
                ldsm4(t1, bd);
                ldsm4(t2, bd + 2560*2);
                kbh[2*bi][0]   = t1[0]; kbh[2*bi][1]   = t1[1];
                kbh[2*bi+1][0] = t1[2]; kbh[2*bi+1][1] = t1[3];
                kbl[2*bi][0]   = t2[0]; kbl[2*bi][1]   = t2[1];
                kbl[2*bi+1][0] = t2[2]; kbl[2*bi+1][1] = t2[3];
            }
            #pragma unroll
            for (int nt = 0; nt < 8; nt++) {
                mma_f16(sc[nt], qah[ks], kbh[nt]);
                mma_f16(sc[nt], qah[ks], kbl[nt]);
                mma_f16(sc[nt], qal[ks], kbh[nt]);
            }
        }

        if (kt == qt) {
            int r0 = w*16 + g, r1 = r0 + 8;
            #pragma unroll
            for (int nt = 0; nt < 8; nt++) {
                int c0 = nt*8 + cq, c1 = c0 + 1;
                if (c0 > r0) sc[nt][0] = -1e30f;
                if (c1 > r0) sc[nt][1] = -1e30f;
                if (c0 > r1) sc[nt][2] = -1e30f;
                if (c1 > r1) sc[nt][3] = -1e30f;
            }
        }

        float t0 = -1e30f, t1 = -1e30f;
        #pragma unroll
        for (int nt = 0; nt < 8; nt++) {
            t0 = fmaxf(t0, fmaxf(sc[nt][0], sc[nt][1]));
            t1 = fmaxf(t1, fmaxf(sc[nt][2], sc[nt][3]));
        }
        t0 = fmaxf(t0, __shfl_xor_sync(0xffffffffu, t0, 1));
        t0 = fmaxf(t0, __shfl_xor_sync(0xffffffffu, t0, 2));
        t1 = fmaxf(t1, __shfl_xor_sync(0xffffffffu, t1, 1));
        t1 = fmaxf(t1, __shfl_xor_sync(0xffffffffu, t1, 2));
        float mn0 = fmaxf(m0, t0), mn1 = fmaxf(m1, t1);
        float cor0 = __expf((m0 - mn0) * scale);
        float cor1 = __expf((m1 - mn1) * scale);
        sum0 *= cor0; sum1 *= cor1;
        #pragma unroll
        for (int nt = 0; nt < 4; nt++) {
            oacc[nt][0] *= cor0; oacc[nt][1] *= cor0;
            oacc[nt][2] *= cor1; oacc[nt][3] *= cor1;
        }
        m0 = mn0; m1 = mn1;

        #pragma unroll
        for (int j = 0; j < 4; j++) {
            float p00 = __expf((sc[2*j][0]   - m0) * scale);
            float p01 = __expf((sc[2*j][1]   - m0) * scale);
            float p02 = __expf((sc[2*j][2]   - m1) * scale);
            float p03 = __expf((sc[2*j][3]   - m1) * scale);
            float p10 = __expf((sc[2*j+1][0] - m0) * scale);
            float p11 = __expf((sc[2*j+1][1] - m0) * scale);
            float p12 = __expf((sc[2*j+1][2] - m1) * scale);
            float p13 = __expf((sc[2*j+1][3] - m1) * scale);
            sum0 += p00 + p01 + p10 + p11;
            sum1 += p02 + p03 + p12 + p13;

            u32 pah[4], pal[4];
            pah[0] = packh2(p00, p01);
            pah[1] = packh2(p02, p03);
            pah[2] = packh2(p10, p11);
            pah[3] = packh2(p12, p13);
            {
                __half2* hp;
                hp = (__half2*)&pah[0];
                pal[0] = packh2(p00 - __half2float(__low2half(*hp)), p01 - __half2float(__high2half(*hp)));
                hp = (__half2*)&pah[1];
                pal[1] = packh2(p02 - __half2float(__low2half(*hp)), p03 - __half2float(__high2half(*hp)));
                hp = (__half2*)&pah[2];
                pal[2] = packh2(p10 - __half2float(__low2half(*hp)), p11 - __half2float(__high2half(*hp)));
                hp = (__half2*)&pah[3];
                pal[3] = packh2(p12 - __half2float(__low2half(*hp)), p13 - __half2float(__high2half(*hp)));
            }

            u32 vbh[4][2], vbl[4][2];
            #pragma unroll
            for (int vp = 0; vp < 2; vp++) {
                int krow = j*16 + (l & 7) + ((l >> 3) & 1) * 8;
                int ncol = vp*16 + (l >> 4) * 8;
                u32 vd = sb + (u32)((stg + 5120 + krow*AP + ncol) * 2);
                u32 t1r[4], t2r[4];
                ldsm4t(t1r, vd);
                ldsm4t(t2r, vd + 2560*2);
                vbh[2*vp][0]   = t1r[0]; vbh[2*vp][1]   = t1r[1];
                vbh[2*vp+1][0] = t1r[2]; vbh[2*vp+1][1] = t1r[3];
                vbl[2*vp][0]   = t2r[0]; vbl[2*vp][1]   = t2r[1];
                vbl[2*vp+1][0] = t2r[2]; vbl[2*vp+1][1] = t2r[3];
            }
            #pragma unroll
            for (int nt = 0; nt < 4; nt++) {
                mma_f16(oacc[nt], pah, vbh[nt]);
                mma_f16(oacc[nt], pah, vbl[nt]);
                mma_f16(oacc[nt], pal, vbh[nt]);
            }
        }
    }
    #undef AT_ISSUE

    sum0 += __shfl_xor_sync(0xffffffffu, sum0, 1);
    sum0 += __shfl_xor_sync(0xffffffffu, sum0, 2);
    sum1 += __shfl_xor_sync(0xffffffffu, sum1, 1);
    sum1 += __shfl_xor_sync(0xffffffffu, sum1, 2);
    float i0 = 1.f / sum0, i1 = 1.f / sum1;
    int tok0 = tb + w*16 + g;
    #pragma unroll
    for (int nt = 0; nt < 4; nt++) {
        int ch = h*HSs + nt*8 + cq;
        float v0 = oacc[nt][0]*i0, v1 = oacc[nt][1]*i0;
        float v2 = oacc[nt][2]*i1, v3 = oacc[nt][3]*i1;
        __half h0 = __float2half_rn(v0), h1 = __float2half_rn(v1);
        __half h2 = __float2half_rn(v2), h3 = __float2half_rn(v3);
        __half l0 = __float2half_rn((v0 - __half2float(h0)) * LOSCALE);
        __half l1 = __float2half_rn((v1 - __half2float(h1)) * LOSCALE);
        __half l2 = __float2half_rn((v2 - __half2float(h2)) * LOSCALE);
        __half l3 = __float2half_rn((v3 - __half2float(h3)) * LOSCALE);
        *(__half2*)(ohg + (size_t)tok0*Cc + ch)     = __halves2half2(h0, h1);
        *(__half2*)(ohg + (size_t)(tok0+8)*Cc + ch) = __halves2half2(h2, h3);
        *(__half2*)(olg + (size_t)tok0*Cc + ch)     = __halves2half2(l0, l1);
        *(__half2*)(olg + (size_t)(tok0+8)*Cc + ch) = __halves2half2(l2, l3);
    }
}

// ---------------- loss (fused path) ----------------
__global__ __launch_bounds__(256) void zero_k() {
    int i = blockIdx.x * 256 + threadIdx.x;
    if (i < BT) g_expsum[i] = 0.f;
    if (i == 0) g_loss = 0.f;
}

__global__ __launch_bounds__(256) void loss_final_k(const float* __restrict__ logits,
                                                    const int* __restrict__ targets) {
    int row = blockIdx.x * 256 + threadIdx.x;
    float lp = logits[(size_t)row * Vv + targets[row]] - logf(g_expsum[row]);
    for (int o = 16; o > 0; o >>= 1) lp += __shfl_down_sync(0xffffffff, lp, o);
    if ((threadIdx.x & 31) == 0) atomicAdd(&g_loss, lp);
}

__global__ void finalize_k(float* out, int extra) {
    float lv = -g_loss / (float)BT;
    for (int i = threadIdx.x + blockIdx.x*blockDim.x; i < extra; i += blockDim.x*gridDim.x)
        out[BTV + i] = lv;
}

// ---------------- host launcher ----------------
static void* symaddr(const void* sym) {
    void* p = nullptr;
    cudaGetSymbolAddress(&p, sym);
    return p;
}

extern "C" void kernel_launch(void* const* d_in, const int* in_sizes, int n_in,
                              void* d_out, int out_size) {
    const int*   idx      = (const int*)  d_in[0];
    const int*   idx_lab  = (const int*)  d_in[1];
    const int*   targets  = (const int*)  d_in[2];
    const float* tok_emb  = (const float*)d_in[3];
    const float* pos_emb  = (const float*)d_in[4];
    const float* lab_emb  = (const float*)d_in[5];
    const float* Wq       = (const float*)d_in[6];
    const float* Wk       = (const float*)d_in[7];
    const float* Wv       = (const float*)d_in[8];
    const float* Wo       = (const float*)d_in[9];
    const float* bo       = (const float*)d_in[10];
    const float* ln1_g    = (const float*)d_in[11];
    const float* ln1_b    = (const float*)d_in[12];
    const float* W1       = (const float*)d_in[13];
    const float* b1       = (const float*)d_in[14];
    const float* W2       = (const float*)d_in[15];
    const float* b2       = (const float*)d_in[16];
    const float* ln2_g    = (const float*)d_in[17];
    const float* ln2_b    = (const float*)d_in[18];
    const float* lnf_g    = (const float*)d_in[19];
    const float* lnf_b    = (const float*)d_in[20];
    const float* Wlm      = (const float*)d_in[21];
    const float* blm      = (const float*)d_in[22];
    float* out = (float*)d_out;

    float*  x    = (float*) symaddr(g_x);
    __half* qkvh = (__half*)symaddr(g_qkvh);
    __half* qkvl = (__half*)symaddr(g_qkvl);
    __half* hh   = (__half*)symaddr(g_hh);
    __half* hl   = (__half*)symaddr(g_hl);
    __half* oh   = (__half*)symaddr(g_oh);
    __half* ol   = (__half*)symaddr(g_ol);
    __half* ffh  = (__half*)symaddr(g_ffh);
    __half* ffl  = (__half*)symaddr(g_ffl);
    float*  esum = (float*) symaddr(g_expsum);
    __half* wqkv_h = (__half*)symaddr(g_wqkv_h);
    __half* wqkv_l = (__half*)symaddr(g_wqkv_l);
    __half* wo_h   = (__half*)symaddr(g_wo_h);
    __half* wo_l   = (__half*)symaddr(g_wo_l);
    __half* w1_h   = (__half*)symaddr(g_w1_h);
    __half* w1_l   = (__half*)symaddr(g_w1_l);
    __half* w2_h   = (__half*)symaddr(g_w2_h);
    __half* w2_l   = (__half*)symaddr(g_w2_l);
    __half* wlm_h  = (__half*)symaddr(g_wlm_h);
    __half* wlm_l  = (__half*)symaddr(g_wlm_l);

    cudaFuncSetAttribute(tgemm_k<false,false,false,true,false,false>, cudaFuncAttributeMaxDynamicSharedMemorySize, TG_SMEM);
    cudaFuncSetAttribute(tgemm_k<true,false,true,false,false,false>,  cudaFuncAttributeMaxDynamicSharedMemorySize, TG_SMEM);
    cudaFuncSetAttribute(tgemm_k<true,true,false,true,false,true>,    cudaFuncAttributeMaxDynamicSharedMemorySize, TG_SMEM);
    cudaFuncSetAttribute(tgemm_k<true,false,false,false,true,false>,  cudaFuncAttributeMaxDynamicSharedMemorySize, TG_SMEM);
    cudaFuncSetAttribute(attn2_k, cudaFuncAttributeMaxDynamicSharedMemorySize, ASMEM);

    prep_k<<<34816, dim3(32, 8)>>>(Wq, Wk, Wv, Wo, W1, W2, Wlm);
    embed_k<<<BT, 128>>>(idx, idx_lab, tok_emb, lab_emb, pos_emb);
    zero_k<<<BT/256, 256>>>();

    dim3 gQKV(NQKV/128, BT/128);   // (12, 64)
    dim3 g512(Cc/128,   BT/128);   // (4, 64)
    dim3 g2048(FFf/128, BT/128);   // (16, 64)
    dim3 gV(Vv/128,     BT/128);   // (64, 64)
    dim3 gattn(Tt/64, Bb*Hh);      // (16, 128)

    for (int l = 0; l < Ll; l++) {
        lnorm_k<<<BT, 128>>>(x, ln1_g + l*Cc, ln1_b + l*Cc, hh, hl);
        tgemm_k<false,false,false,true,false,false><<<gQKV, 256, TG_SMEM>>>(
            hh, hl, wqkv_h + (size_t)l*NQKV*Cc, wqkv_l + (size_t)l*NQKV*Cc,
            nullptr, nullptr, nullptr, qkvh, qkvl, nullptr, BT, NQKV, Cc);
        attn2_k<<<gattn, 128, ASMEM>>>(qkvh, qkvl, oh, ol);
        tgemm_k<true,false,true,false,false,false><<<g512, 256, TG_SMEM>>>(
            oh, ol, wo_h + (size_t)l*Cc*Cc, wo_l + (size_t)l*Cc*Cc,
            bo + l*Cc, x, x, nullptr, nullptr, nullptr, BT, Cc, Cc);
        lnorm_k<<<BT, 128>>>(x, ln2_g + l*Cc, ln2_b + l*Cc, hh, hl);
        tgemm_k<true,true,false,true,false,true><<<g2048, 256, TG_SMEM>>>(
            hh, hl, w1_h + (size_t)l*FFf*Cc, w1_l + (size_t)l*FFf*Cc,
            b1 + l*FFf, nullptr, nullptr, ffh, ffl, nullptr, BT, FFf, Cc);
        tgemm_k<true,false,true,false,false,false><<<g512, 256, TG_SMEM>>>(
            ffh, ffl, w2_h + (size_t)l*Cc*FFf, w2_l + (size_t)l*Cc*FFf,
            b2 + l*Cc, x, x, nullptr, nullptr, nullptr, BT, Cc, FFf);
    }
    lnorm_k<<<BT, 128>>>(x, lnf_g, lnf_b, hh, hl);
    tgemm_k<true,false,false,false,true,false><<<gV, 256, TG_SMEM>>>(
        hh, hl, wlm_h, wlm_l, blm, nullptr, out, nullptr, nullptr, esum, BT, Vv, Cc);

    loss_final_k<<<BT/256, 256>>>(out, targets);
    int extra = out_size - (int)BTV;
    if (extra > 0) finalize_k<<<1, 128>>>(out, extra);
}

// round 15
// speedup vs baseline: 1.2157x; 1.2157x over previous
#include <cuda_runtime.h>
#include <cuda_fp16.h>
#include <cstdint>
#include <math.h>

// ---------------- problem constants ----------------
#define Vv 8192
#define Cc 512
#define Hh 16
#define HSs 32
#define Ll 12
#define FFf 2048
#define Bb 8
#define Tt 1024
#define BT (Bb*Tt)              // 8192
#define BTV ((size_t)BT * Vv)   // 67108864
#define NQKV 1536

typedef unsigned int u32;
typedef unsigned long long u64;

// ---------------- scratch (device globals, no allocation) ----------------
__device__ float  g_x   [BT*Cc];     // residual stream, fp32
__device__ __half g_qkvh[BT*NQKV];   // qkv hi
__device__ __half g_qkvl[BT*NQKV];   // qkv lo
__device__ __half g_hh  [BT*Cc];
__device__ __half g_hl  [BT*Cc];
__device__ __half g_oh  [BT*Cc];
__device__ __half g_ol  [BT*Cc];
__device__ __half g_ffh [BT*FFf];
__device__ __half g_ffl [BT*FFf];
__device__ float  g_expsum[BT];
__device__ float  g_loss;

// split fp16 weights, [N][K] layout per layer
__device__ __half g_wqkv_h[Ll*NQKV*Cc];
__device__ __half g_wqkv_l[Ll*NQKV*Cc];
__device__ __half g_wo_h  [Ll*Cc*Cc];
__device__ __half g_wo_l  [Ll*Cc*Cc];
__device__ __half g_w1_h  [Ll*FFf*Cc];
__device__ __half g_w1_l  [Ll*FFf*Cc];
__device__ __half g_w2_h  [Ll*Cc*FFf];
__device__ __half g_w2_l  [Ll*Cc*FFf];
__device__ __half g_wlm_h [Vv*Cc];
__device__ __half g_wlm_l [Vv*Cc];

// ---------------- asm wrappers ----------------
__device__ __forceinline__ void mma_f16(float* d, const u32* a, const u32* b) {
    asm volatile("mma.sync.aligned.m16n8k16.row.col.f32.f16.f16.f32 "
        "{%0,%1,%2,%3}, {%4,%5,%6,%7}, {%8,%9}, {%0,%1,%2,%3};"
        : "+f"(d[0]), "+f"(d[1]), "+f"(d[2]), "+f"(d[3])
        : "r"(a[0]), "r"(a[1]), "r"(a[2]), "r"(a[3]),
          "r"(b[0]), "r"(b[1]));
}
__device__ __forceinline__ void ldsm4(u32* r, u32 addr) {
    asm volatile("ldmatrix.sync.aligned.m8n8.x4.shared.b16 "
        "{%0,%1,%2,%3}, [%4];"
        : "=r"(r[0]), "=r"(r[1]), "=r"(r[2]), "=r"(r[3]) : "r"(addr));
}
__device__ __forceinline__ void ldsm4t(u32* r, u32 addr) {
    asm volatile("ldmatrix.sync.aligned.m8n8.x4.trans.shared.b16 "
        "{%0,%1,%2,%3}, [%4];"
        : "=r"(r[0]), "=r"(r[1]), "=r"(r[2]), "=r"(r[3]) : "r"(addr));
}
__device__ __forceinline__ void cpa16(u32 dst, const void* src) {
    asm volatile("cp.async.cg.shared.global [%0], [%1], 16;" :: "r"(dst), "l"(src));
}
__device__ __forceinline__ void cp_commit() {
    asm volatile("cp.async.commit_group;" ::: "memory");
}
template<int N>
__device__ __forceinline__ void cp_wait() {
    asm volatile("cp.async.wait_group %0;" :: "n"(N) : "memory");
}
__device__ __forceinline__ u32 packh2(float x, float y) {
    __half2 h = __halves2half2(__float2half_rn(x), __float2half_rn(y));
    return *(u32*)&h;
}

// ---------------- fused weight prep ----------------
__device__ __forceinline__ void tsplit_tile(const float* __restrict__ src,
                                            __half* __restrict__ hi,
                                            __half* __restrict__ lo,
                                            int K, int N, int n0, int k0,
                                            float (*t)[33], int tx, int ty) {
    #pragma unroll
    for (int r = 0; r < 4; r++)
        t[ty + 8*r][tx] = src[(size_t)(k0 + ty + 8*r) * N + n0 + tx];
    __syncthreads();
    #pragma unroll
    for (int r = 0; r < 4; r++) {
        int n = ty + 8*r;
        float v = t[tx][n];
        __half vh = __float2half_rn(v);
        __half vl = __float2half_rn(v - __half2float(vh));
        size_t o = (size_t)(n0 + n) * K + k0 + tx;
        hi[o] = vh; lo[o] = vl;
    }
}

__global__ __launch_bounds__(256) void prep_k(const float* __restrict__ Wq,
                                              const float* __restrict__ Wk,
                                              const float* __restrict__ Wv,
                                              const float* __restrict__ Wo,
                                              const float* __restrict__ W1,
                                              const float* __restrict__ W2,
                                              const float* __restrict__ Wlm) {
    __shared__ float t[32][33];
    int b = blockIdx.x;
    int tx = threadIdx.x, ty = threadIdx.y;
    if (b < 3072) {
        int c0 = (b & 15) * 32, h = (b >> 4) & 15, l = b >> 8;
        const float* srcs[3] = {Wq, Wk, Wv};
        for (int s = 0; s < 3; s++) {
            const float* src = srcs[s] + ((size_t)(l*Hh + h) * Cc) * HSs;
            #pragma unroll
            for (int r = 0; r < 4; r++)
                t[ty + 8*r][tx] = src[(size_t)(c0 + ty + 8*r) * HSs + tx];
            __syncthreads();
            size_t nbase = (size_t)l * NQKV + s * 512 + h * 32;
            #pragma unroll
            for (int r = 0; r < 4; r++) {
                int d = ty + 8*r;
                float v = t[tx][d];
                __half hi = __float2half_rn(v);
                __half lo = __float2half_rn(v - __half2float(hi));
                size_t o = (nbase + d) * Cc + c0 + tx;
                g_wqkv_h[o] = hi; g_wqkv_l[o] = lo;
            }
            __syncthreads();
        }
    } else if (b < 6144) {
        b -= 3072;
        int l = b >> 8, n0 = (b & 15) * 32, k0 = ((b >> 4) & 15) * 32;
        tsplit_tile(Wo + (size_t)l*Cc*Cc, g_wo_h + (size_t)l*Cc*Cc, g_wo_l + (size_t)l*Cc*Cc,
                    Cc, Cc, n0, k0, t, tx, ty);
    } else if (b < 18432) {
        b -= 6144;
        int l = b >> 10, rem = b & 1023;
        int n0 = (rem & 63) * 32, k0 = (rem >> 6) * 32;
        tsplit_tile(W1 + (size_t)l*Cc*FFf, g_w1_h + (size_t)l*FFf*Cc, g_w1_l + (size_t)l*FFf*Cc,
                    Cc, FFf, n0, k0, t, tx, ty);
    } else if (b < 30720) {
        b -= 18432;
        int l = b >> 10, rem = b & 1023;
        int n0 = (rem & 15) * 32, k0 = (rem >> 4) * 32;
        tsplit_tile(W2 + (size_t)l*FFf*Cc, g_w2_h + (size_t)l*Cc*FFf, g_w2_l + (size_t)l*Cc*FFf,
                    FFf, Cc, n0, k0, t, tx, ty);
    } else {
        b -= 30720;
        int n0 = (b & 255) * 32, k0 = (b >> 8) * 32;
        tsplit_tile(Wlm, g_wlm_h, g_wlm_l, Cc, Vv, n0, k0, t, tx, ty);
    }
}

// ---------------- embedding (+ zero expsum/loss) ----------------
__global__ __launch_bounds__(128) void embed_k(const int* __restrict__ idx,
                                               const int* __restrict__ lab,
                                               const float* __restrict__ tok_emb,
                                               const float* __restrict__ lab_emb,
                                               const float* __restrict__ pos_emb) {
    int i = blockIdx.x;
    if (threadIdx.x == 0) {
        g_expsum[i] = 0.f;
        if (i == 0) g_loss = 0.f;
    }
    int t = i & (Tt-1);
    int ix = idx[i];
    int lb = lab[i];
    const float4* te = (const float4*)(tok_emb + (size_t)ix*Cc);
    const float4* le = (const float4*)(lab_emb + (size_t)lb*Cc);
    const float4* pe = (const float4*)(pos_emb + (size_t)t *Cc);
    float4* xo = (float4*)(g_x + (size_t)i*Cc);
    int c = threadIdx.x;
    float4 a = te[c], b = le[c], p = pe[c];
    xo[c] = make_float4(a.x+b.x+p.x, a.y+b.y+p.y, a.z+b.z+p.z, a.w+b.w+p.w);
}

// ---------------- layernorm: fp32 in -> fp16 hi/lo out ----------------
__global__ __launch_bounds__(128) void lnorm_k(const float* __restrict__ x,
                                               const float* __restrict__ g,
                                               const float* __restrict__ b,
                                               __half* __restrict__ yh,
                                               __half* __restrict__ yl) {
    int row = blockIdx.x;
    const float4* xr = (const float4*)(x + (size_t)row*Cc);
    float4 v = xr[threadIdx.x];
    float s  = v.x+v.y+v.z+v.w;
    float s2 = v.x*v.x + v.y*v.y + v.z*v.z + v.w*v.w;
    for (int o = 16; o > 0; o >>= 1) {
        s  += __shfl_down_sync(0xffffffff, s,  o);
        s2 += __shfl_down_sync(0xffffffff, s2, o);
    }
    __shared__ float sh[4], sh2[4];
    int wid = threadIdx.x >> 5, lane = threadIdx.x & 31;
    if (lane == 0) { sh[wid] = s; sh2[wid] = s2; }
    __syncthreads();
    __shared__ float smean, srstd;
    if (threadIdx.x == 0) {
        float ts = sh[0]+sh[1]+sh[2]+sh[3];
        float ts2 = sh2[0]+sh2[1]+sh2[2]+sh2[3];
        float mean = ts * (1.0f/Cc);
        float var = ts2 * (1.0f/Cc) - mean*mean;
        smean = mean;
        srstd = rsqrtf(var + 1e-5f);
    }
    __syncthreads();
    float mean = smean, rstd = srstd;
    int c = threadIdx.x * 4;
    float4 gg = *(const float4*)(g + c);
    float4 bb = *(const float4*)(b + c);
    float ov[4];
    ov[0] = (v.x-mean)*rstd*gg.x + bb.x;
    ov[1] = (v.y-mean)*rstd*gg.y + bb.y;
    ov[2] = (v.z-mean)*rstd*gg.z + bb.z;
    ov[3] = (v.w-mean)*rstd*gg.w + bb.w;
    __half hv[4], lv[4];
    #pragma unroll
    for (int e = 0; e < 4; e++) {
        hv[e] = __float2half_rn(ov[e]);
        lv[e] = __float2half_rn(ov[e] - __half2float(hv[e]));
    }
    *(uint2*)(yh + (size_t)row*Cc + c) = *(uint2*)hv;
    *(uint2*)(yl + (size_t)row*Cc + c) = *(uint2*)lv;
}

// ---------------- GEMM: fp16x3 on HMMA (BL=false -> fp16x2, no B-lo) ----------------
#define SAL_B 10240
#define SBH_B 20480
#define SBL_B 30720
#define STG_B 40960
#define TG_SMEM (2*STG_B)

template<bool BIAS, bool RELU, bool RES, bool SPLIT, bool EXPS, bool BL>
__global__ __launch_bounds__(256, 2) void tgemm_k(const __half* __restrict__ Ahg,
                                                  const __half* __restrict__ Alg,
                                                  const __half* __restrict__ Bhg,
                                                  const __half* __restrict__ Blg,
                                                  const float* __restrict__ bias,
                                                  const float* __restrict__ res,
                                                  float* __restrict__ Cf,
                                                  __half* __restrict__ Ch,
                                                  __half* __restrict__ Cl,
                                                  float* __restrict__ expsum,
                                                  int M, int N, int K) {
    extern __shared__ __half smd[];
    const int tid = threadIdx.x;
    const int lane = tid & 31, w = tid >> 5;
    const int row0 = blockIdx.y * 128, col0 = blockIdx.x * 128;
    const int m0w = (w >> 2) * 64, n0w = (w & 3) * 32;
    const u32 sb = (u32)__cvta_generic_to_shared(smd);

    float acc[4][4][4];
    #pragma unroll
    for (int i = 0; i < 4; i++)
        #pragma unroll
        for (int j = 0; j < 4; j++)
            #pragma unroll
            for (int e = 0; e < 4; e++) acc[i][j][e] = 0.f;

    const int nk = K >> 5;
    const int r = tid >> 1;
    const int hofs = (tid & 1) << 4;
    const __half* aHp = Ahg + (size_t)(row0 + r) * K + hofs;
    const __half* aLp = Alg + (size_t)(row0 + r) * K + hofs;
    const __half* bHp = Bhg + (size_t)(col0 + r) * K + hofs;
    const __half* bLp = BL ? (Blg + (size_t)(col0 + r) * K + hofs) : nullptr;
    const u32 dstA = sb + (u32)(r * 80 + hofs * 2);

    #define TG_ISSUE(bufbyte, kc) do {                                   \
        int _ko = (kc) << 5;                                             \
        u32 _d = dstA + (bufbyte);                                       \
        cpa16(_d,                 aHp + _ko);                            \
        cpa16(_d + 16,            aHp + _ko + 8);                        \
        cpa16(_d + SAL_B,         aLp + _ko);                            \
        cpa16(_d + SAL_B + 16,    aLp + _ko + 8);                        \
        cpa16(_d + SBH_B,         bHp + _ko);                            \
        cpa16(_d + SBH_B + 16,    bHp + _ko + 8);                        \
        if (BL) {                                                        \
            cpa16(_d + SBL_B,         bLp + _ko);                        \
            cpa16(_d + SBL_B + 16,    bLp + _ko + 8);                    \
        }                                                                \
    } while (0)

    TG_ISSUE(0, 0);
    cp_commit();

    const int lr = lane & 7, lg1 = (lane >> 3) & 1, lg2 = lane >> 4;

    for (int kt = 0; kt < nk; kt++) {
        const u32 cur = (u32)((kt & 1) * STG_B);
        cp_wait<0>();
        __syncthreads();
        if (kt + 1 < nk) {
            TG_ISSUE((u32)(((kt + 1) & 1) * STG_B), kt + 1);
            cp_commit();
        }

        #pragma unroll
        for (int ks = 0; ks < 32; ks += 16) {
            u32 afh[4][4], afl[4][4];
            #pragma unroll
            for (int mi = 0; mi < 4; mi++) {
                int row = m0w + mi*16 + lr + lg1*8;
                u32 ad = sb + cur + (u32)((row*40 + ks + lg2*8) * 2);
                ldsm4(afh[mi], ad);
                ldsm4(afl[mi], ad + SAL_B);
            }
            u32 bfh[4][2], bfl[4][2];
            #pragma unroll
            for (int bi = 0; bi < 2; bi++) {
                int n = n0w + bi*16 + lr + lg2*8;
                u32 bd = sb + cur + SBH_B + (u32)((n*40 + ks + lg1*8) * 2);
                u32 t1[4];
                ldsm4(t1, bd);
                bfh[2*bi][0]   = t1[0]; bfh[2*bi][1]   = t1[1];
                bfh[2*bi+1][0] = t1[2]; bfh[2*bi+1][1] = t1[3];
                if (BL) {
                    u32 t2[4];
                    ldsm4(t2, bd + (SBL_B - SBH_B));
                    bfl[2*bi][0]   = t2[0]; bfl[2*bi][1]   = t2[1];
                    bfl[2*bi+1][0] = t2[2]; bfl[2*bi+1][1] = t2[3];
                }
            }
            #pragma unroll
            for (int mi = 0; mi < 4; mi++)
                #pragma unroll
                for (int ni = 0; ni < 4; ni++) {
                    mma_f16(acc[mi][ni], afh[mi], bfh[ni]);
                    if (BL) mma_f16(acc[mi][ni], afh[mi], bfl[ni]);
                    mma_f16(acc[mi][ni], afl[mi], bfh[ni]);
                }
        }
    }
    #undef TG_ISSUE

    #pragma unroll
    for (int mi = 0; mi < 4; mi++) {
        int r0 = row0 + m0w + mi*16 + (lane >> 2);
        float es0 = 0.f, es1 = 0.f;
        #pragma unroll
        for (int ni = 0; ni < 4; ni++) {
            int cc = col0 + n0w + ni*8 + (lane & 3)*2;
            float2 v0 = make_float2(acc[mi][ni][0], acc[mi][ni][1]);
            float2 v1 = make_float2(acc[mi][ni][2], acc[mi][ni][3]);
            if (BIAS) {
                float2 bb = *(const float2*)(bias + cc);
                v0.x += bb.x; v0.y += bb.y; v1.x += bb.x; v1.y += bb.y;
            }
            if (RELU) {
                v0.x = fmaxf(v0.x, 0.f); v0.y = fmaxf(v0.y, 0.f);
                v1.x = fmaxf(v1.x, 0.f); v1.y = fmaxf(v1.y, 0.f);
            }
            if (RES) {
                float2 ra = *(const float2*)(res + (size_t)r0*N + cc);
                float2 rb = *(const float2*)(res + (size_t)(r0+8)*N + cc);
                v0.x += ra.x; v0.y += ra.y; v1.x += rb.x; v1.y += rb.y;
            }
            if (SPLIT) {
                __half h0 = __float2half_rn(v0.x), h1 = __float2half_rn(v0.y);
                __half h2 = __float2half_rn(v1.x), h3 = __float2half_rn(v1.y);
                __half l0 = __float2half_rn(v0.x - __half2float(h0));
                __half l1 = __float2half_rn(v0.y - __half2float(h1));
                __half l2 = __float2half_rn(v1.x - __half2float(h2));
                __half l3 = __float2half_rn(v1.y - __half2float(h3));
                *(__half2*)(Ch + (size_t)r0*N + cc)     = __halves2half2(h0, h1);
                *(__half2*)(Ch + (size_t)(r0+8)*N + cc) = __halves2half2(h2, h3);
                *(__half2*)(Cl + (size_t)r0*N + cc)     = __halves2half2(l0, l1);
                *(__half2*)(Cl + (size_t)(r0+8)*N + cc) = __halves2half2(l2, l3);
            } else {
                *(float2*)(Cf + (size_t)r0*N + cc) = v0;
                *(float2*)(Cf + (size_t)(r0+8)*N + cc) = v1;
            }
            if (EXPS) {
                es0 += __expf(v0.x) + __expf(v0.y);
                es1 += __expf(v1.x) + __expf(v1.y);
            }
        }
        if (EXPS) {
            es0 += __shfl_xor_sync(0xffffffffu, es0, 1);
            es0 += __shfl_xor_sync(0xffffffffu, es0, 2);
            es1 += __shfl_xor_sync(0xffffffffu, es1, 1);
            es1 += __shfl_xor_sync(0xffffffffu, es1, 2);
            if ((lane & 3) == 0) {
                atomicAdd(&expsum[r0], es0);
                atomicAdd(&expsum[r0 + 8], es1);
            }
        }
    }
}

// ---------------- tensor-core causal flash attention ----------------
#define AP 40
#define ASMEM (25600*2)

__global__ __launch_bounds__(128) void attn2_k(const __half* __restrict__ qkvh,
                                               const __half* __restrict__ qkvl,
                                               __half* __restrict__ ohg,
                                               __half* __restrict__ olg) {
    extern __shared__ __half ash[];
    const u32 sb = (u32)__cvta_generic_to_shared(ash);
    const int tid = threadIdx.x;
    const int l = tid & 31, w = tid >> 5;
    const int bh = blockIdx.y, b = bh >> 4, h = bh & 15;
    const int qt = (int)gridDim.x - 1 - (int)blockIdx.x;
    const float scale = 0.17677669529663689f;

    const int tb = b*Tt + qt*64;
    const int rr = tid >> 1;
    const int ss = tid & 1;

    {
        const __half* qh = qkvh + (size_t)(tb + rr)*NQKV + h*HSs + ss*16;
        const __half* ql = qkvl + (size_t)(tb + rr)*NQKV + h*HSs + ss*16;
        u32 d = sb + (u32)((rr*AP + ss*16) * 2);
        cpa16(d, qh);              cpa16(d + 16, qh + 8);
        cpa16(d + 2560*2, ql);     cpa16(d + 2560*2 + 16, ql + 8);
    }
    #define AT_ISSUE(stgh, kt) do {                                          \
        int _tok = b*Tt + (kt)*64 + rr;                                      \
        const __half* _kh = qkvh + (size_t)_tok*NQKV + 512  + h*HSs + ss*16; \
        const __half* _kl = qkvl + (size_t)_tok*NQKV + 512  + h*HSs + ss*16; \
        const __half* _vh = qkvh + (size_t)_tok*NQKV + 1024 + h*HSs + ss*16; \
        const __half* _vl = qkvl + (size_t)_tok*NQKV + 1024 + h*HSs + ss*16; \
        u32 _d = sb + (u32)(((stgh) + rr*AP + ss*16) * 2);                   \
        cpa16(_d, _kh);               cpa16(_d + 16, _kh + 8);               \
        cpa16(_d + 2560*2, _kl);      cpa16(_d + 2560*2 + 16, _kl + 8);      \
        cpa16(_d + 5120*2, _vh);      cpa16(_d + 5120*2 + 16, _vh + 8);      \
        cpa16(_d + 7680*2, _vl);      cpa16(_d + 7680*2 + 16, _vl + 8);      \
    } while (0)

    AT_ISSUE(5120, 0);
    cp_commit();

    const int lr = l & 7, lg1 = (l >> 3) & 1, lg2 = l >> 4;
    const int g = l >> 2;
    const int cq = (l & 3) * 2;

    u32 qah[2][4], qal[2][4];
    float m0 = -1e30f, m1 = -1e30f, sum0 = 0.f, sum1 = 0.f;
    float oacc[4][4];
    #pragma unroll
    for (int i = 0; i < 4; i++)
        #pragma unroll
        for (int e = 0; e < 4; e++) oacc[i][e] = 0.f;

    for (int kt = 0; kt <= qt; kt++) {
        const u32 stg = (u32)(5120 + (kt & 1) * 10240);
        cp_wait<0>();
        __syncthreads();
        if (kt < qt) { AT_ISSUE((u32)(5120 + ((kt+1) & 1) * 10240), kt + 1); cp_commit(); }
        if (kt == 0) {
            #pragma unroll
            for (int ks = 0; ks < 2; ks++) {
                int row = w*16 + lr + lg1*8;
                u32 ad = sb + (u32)((row*AP + ks*16 + lg2*8) * 2);
                ldsm4(qah[ks], ad);
                ldsm4(qal[ks], ad + 2560*2);
            }
        }

        float sc[8][4];
        #pragma unroll
        for (int nt = 0; nt < 8; nt++)
            #pragma unroll
            for (int e = 0; e < 4; e++) sc[nt][e] = 0.f;

        #pragma unroll
        for (int ks = 0; ks < 2; ks++) {
            u32 kbh[8][2], kbl[8][2];
            #pragma unroll
            for (int bi = 0; bi < 4; bi++) {
                int n = bi*16 + lr + lg2*8;
                u32 bd = sb + (u32)((stg + n*AP + ks*16 + lg1*8) * 2);
                u32 t1[4], t2[4];
                ldsm4(t1, bd);
                ldsm4(t2, bd + 2560*2);
                kbh[2*bi][0]   = t1[0]; kbh[2*bi][1]   = t1[1];
                kbh[2*bi+1][0] = t1[2]; kbh[2*bi+1][1] = t1[3];
                kbl[2*bi][0]   = t2[0]; kbl[2*bi][1]   = t2[1];
                kbl[2*bi+1][0] = t2[2]; kbl[2*bi+1][1] = t2[3];
            }
            #pragma unroll
            for (int nt = 0; nt < 8; nt++) {
                mma_f16(sc[nt], qah[ks], kbh[nt]);
                mma_f16(sc[nt], qah[ks], kbl[nt]);
                mma_f16(sc[nt], qal[ks], kbh[nt]);
            }
        }

        if (kt == qt) {
            int r0 = w*16 + g, r1 = r0 + 8;
            #pragma unroll
            for (int nt = 0; nt < 8; nt++) {
                int c0 = nt*8 + cq, c1 = c0 + 1;
                if (c0 > r0) sc[nt][0] = -1e30f;
                if (c1 > r0) sc[nt][1] = -1e30f;
                if (c0 > r1) sc[nt][2] = -1e30f;
                if (c1 > r1) sc[nt][3] = -1e30f;
            }
        }

        float t0 = -1e30f, t1 = -1e30f;
        #pragma unroll
        for (int nt = 0; nt < 8; nt++) {
            t0 = fmaxf(t0, fmaxf(sc[nt][0], sc[nt][1]));
            t1 = fmaxf(t1, fmaxf(sc[nt][2], sc[nt][3]));
        }
        t0 = fmaxf(t0, __shfl_xor_sync(0xffffffffu, t0, 1));
        t0 = fmaxf(t0, __shfl_xor_sync(0xffffffffu, t0, 2));
        t1 = fmaxf(t1, __shfl_xor_sync(0xffffffffu, t1, 1));
        t1 = fmaxf(t1, __shfl_xor_sync(0xffffffffu, t1, 2));
        float mn0 = fmaxf(m0, t0), mn1 = fmaxf(m1, t1);
        float cor0 = __expf((m0 - mn0) * scale);
        float cor1 = __expf((m1 - mn1) * scale);
        sum0 *= cor0; sum1 *= cor1;
        #pragma unroll
        for (int nt = 0; nt < 4; nt++) {
            oacc[nt][0] *= cor0; oacc[nt][1] *= cor0;
            oacc[nt][2] *= cor1; oacc[nt][3] *= cor1;
        }
        m0 = mn0; m1 = mn1;

        #pragma unroll
        for (int j = 0; j < 4; j++) {
            float p00 = __expf((sc[2*j][0]   - m0) * scale);
            float p01 = __expf((sc[2*j][1]   - m0) * scale);
            float p02 = __expf((sc[2*j][2]   - m1) * scale);
            float p03 = __expf((sc[2*j][3]   - m1) * scale);
            float p10 = __expf((sc[2*j+1][0] - m0) * scale);
            float p11 = __expf((sc[2*j+1][1] - m0) * scale);
            float p12 = __expf((sc[2*j+1][2] - m1) * scale);
            float p13 = __expf((sc[2*j+1][3] - m1) * scale);
            sum0 += p00 + p01 + p10 + p11;
            sum1 += p02 + p03 + p12 + p13;

            u32 pah[4], pal[4];
            pah[0] = packh2(p00, p01);
            pah[1] = packh2(p02, p03);
            pah[2] = packh2(p10, p11);
            pah[3] = packh2(p12, p13);
            {
                __half2* hp;
                hp = (__half2*)&pah[0];
                pal[0] = packh2(p00 - __half2float(__low2half(*hp)), p01 - __half2float(__high2half(*hp)));
                hp = (__half2*)&pah[1];
                pal[1] = packh2(p02 - __half2float(__low2half(*hp)), p03 - __half2float(__high2half(*hp)));
                hp = (__half2*)&pah[2];
                pal[2] = packh2(p10 - __half2float(__low2half(*hp)), p11 - __half2float(__high2half(*hp)));
                hp = (__half2*)&pah[3];
                pal[3] = packh2(p12 - __half2float(__low2half(*hp)), p13 - __half2float(__high2half(*hp)));
            }

            u32 vbh[4][2], vbl[4][2];
            #pragma unroll
            for (int vp = 0; vp < 2; vp++) {
                int krow = j*16 + (l & 7) + ((l >> 3) & 1) * 8;
                int ncol = vp*16 + (l >> 4) * 8;
                u32 vd = sb + (u32)((stg + 5120 + krow*AP + ncol) * 2);
                u32 t1r[4], t2r[4];
                ldsm4t(t1r, vd);
                ldsm4t(t2r, vd + 2560*2);
                vbh[2*vp][0]   = t1r[0]; vbh[2*vp][1]   = t1r[1];
                vbh[2*vp+1][0] = t1r[2]; vbh[2*vp+1][1] = t1r[3];
                vbl[2*vp][0]   = t2r[0]; vbl[2*vp][1]   = t2r[1];
                vbl[2*vp+1][0] = t2r[2]; vbl[2*vp+1][1] = t2r[3];
            }
            #pragma unroll
            for (int nt = 0; nt < 4; nt++) {
                mma_f16(oacc[nt], pah, vbh[nt]);
                mma_f16(oacc[nt], pah, vbl[nt]);
                mma_f16(oacc[nt], pal, vbh[nt]);
            }
        }
    }
    #undef AT_ISSUE

    sum0 += __shfl_xor_sync(0xffffffffu, sum0, 1);
    sum0 += __shfl_xor_sync(0xffffffffu, sum0, 2);
    sum1 += __shfl_xor_sync(0xffffffffu, sum1, 1);
    sum1 += __shfl_xor_sync(0xffffffffu, sum1, 2);
    float i0 = 1.f / sum0, i1 = 1.f / sum1;
    int tok0 = tb + w*16 + g;
    #pragma unroll
    for (int nt = 0; nt < 4; nt++) {
        int ch = h*HSs + nt*8 + cq;
        float v0 = oacc[nt][0]*i0, v1 = oacc[nt][1]*i0;
        float v2 = oacc[nt][2]*i1, v3 = oacc[nt][3]*i1;
        __half h0 = __float2half_rn(v0), h1 = __float2half_rn(v1);
        __half h2 = __float2half_rn(v2), h3 = __float2half_rn(v3);
        __half l0 = __float2half_rn(v0 - __half2float(h0));
        __half l1 = __float2half_rn(v1 - __half2float(h1));
        __half l2 = __float2half_rn(v2 - __half2float(h2));
        __half l3 = __float2half_rn(v3 - __half2float(h3));
        *(__half2*)(ohg + (size_t)tok0*Cc + ch)     = __halves2half2(h0, h1);
        *(__half2*)(ohg + (size_t)(tok0+8)*Cc + ch) = __halves2half2(h2, h3);
        *(__half2*)(olg + (size_t)tok0*Cc + ch)     = __halves2half2(l0, l1);
        *(__half2*)(olg + (size_t)(tok0+8)*Cc + ch) = __halves2half2(l2, l3);
    }
}

// ---------------- loss (fused path) ----------------
__global__ __launch_bounds__(256) void loss_final_k(const float* __restrict__ logits,
                                                    const int* __restrict__ targets) {
    int row = blockIdx.x * 256 + threadIdx.x;
    float lp = logits[(size_t)row * Vv + targets[row]] - logf(g_expsum[row]);
    for (int o = 16; o > 0; o >>= 1) lp += __shfl_down_sync(0xffffffff, lp, o);
    if ((threadIdx.x & 31) == 0) atomicAdd(&g_loss, lp);
}

__global__ void finalize_k(float* out, int extra) {
    float lv = -g_loss / (float)BT;
    for (int i = threadIdx.x + blockIdx.x*blockDim.x; i < extra; i += blockDim.x*gridDim.x)
        out[BTV + i] = lv;
}

// ---------------- host launcher ----------------
static void* symaddr(const void* sym) {
    void* p = nullptr;
    cudaGetSymbolAddress(&p, sym);
    return p;
}

extern "C" void kernel_launch(void* const* d_in, const int* in_sizes, int n_in,
                              void* d_out, int out_size) {
    const int*   idx      = (const int*)  d_in[0];
    const int*   idx_lab  = (const int*)  d_in[1];
    const int*   targets  = (const int*)  d_in[2];
    const float* tok_emb  = (const float*)d_in[3];
    const float* pos_emb  = (const float*)d_in[4];
    const float* lab_emb  = (const float*)d_in[5];
    const float* Wq       = (const float*)d_in[6];
    const float* Wk       = (const float*)d_in[7];
    const float* Wv       = (const float*)d_in[8];
    const float* Wo       = (const float*)d_in[9];
    const float* bo       = (const float*)d_in[10];
    const float* ln1_g    = (const float*)d_in[11];
    const float* ln1_b    = (const float*)d_in[12];
    const float* W1       = (const float*)d_in[13];
    const float* b1       = (const float*)d_in[14];
    const float* W2       = (const float*)d_in[15];
    const float* b2       = (const float*)d_in[16];
    const float* ln2_g    = (const float*)d_in[17];
    const float* ln2_b    = (const float*)d_in[18];
    const float* lnf_g    = (const float*)d_in[19];
    const float* lnf_b    = (const float*)d_in[20];
    const float* Wlm      = (const float*)d_in[21];
    const float* blm      = (const float*)d_in[22];
    float* out = (float*)d_out;

    float*  x    = (float*) symaddr(g_x);
    __half* qkvh = (__half*)symaddr(g_qkvh);
    __half* qkvl = (__half*)symaddr(g_qkvl);
    __half* hh   = (__half*)symaddr(g_hh);
    __half* hl   = (__half*)symaddr(g_hl);
    __half* oh   = (__half*)symaddr(g_oh);
    __half* ol   = (__half*)symaddr(g_ol);
    __half* ffh  = (__half*)symaddr(g_ffh);
    __half* ffl  = (__half*)symaddr(g_ffl);
    float*  esum = (float*) symaddr(g_expsum);
    __half* wqkv_h = (__half*)symaddr(g_wqkv_h);
    __half* wqkv_l = (__half*)symaddr(g_wqkv_l);
    __half* wo_h   = (__half*)symaddr(g_wo_h);
    __half* wo_l   = (__half*)symaddr(g_wo_l);
    __half* w1_h   = (__half*)symaddr(g_w1_h);
    __half* w1_l   = (__half*)symaddr(g_w1_l);
    __half* w2_h   = (__half*)symaddr(g_w2_h);
    __half* w2_l   = (__half*)symaddr(g_w2_l);
    __half* wlm_h  = (__half*)symaddr(g_wlm_h);
    __half* wlm_l  = (__half*)symaddr(g_wlm_l);

    cudaFuncSetAttribute(tgemm_k<false,false,false,true,false,true>, cudaFuncAttributeMaxDynamicSharedMemorySize, TG_SMEM);
    cudaFuncSetAttribute(tgemm_k<true,false,true,false,false,true>,  cudaFuncAttributeMaxDynamicSharedMemorySize, TG_SMEM);
    cudaFuncSetAttribute(tgemm_k<true,true,false,true,false,true>,   cudaFuncAttributeMaxDynamicSharedMemorySize, TG_SMEM);
    cudaFuncSetAttribute(tgemm_k<true,false,false,false,true,false>, cudaFuncAttributeMaxDynamicSharedMemorySize, TG_SMEM);
    cudaFuncSetAttribute(attn2_k, cudaFuncAttributeMaxDynamicSharedMemorySize, ASMEM);

    prep_k<<<34816, dim3(32, 8)>>>(Wq, Wk, Wv, Wo, W1, W2, Wlm);
    embed_k<<<BT, 128>>>(idx, idx_lab, tok_emb, lab_emb, pos_emb);

    dim3 gQKV(NQKV/128, BT/128);   // (12, 64)
    dim3 g512(Cc/128,   BT/128);   // (4, 64)
    dim3 g2048(FFf/128, BT/128);   // (16, 64)
    dim3 gV(Vv/128,     BT/128);   // (64, 64)
    dim3 gattn(Tt/64, Bb*Hh);      // (16, 128)

    for (int l = 0; l < Ll; l++) {
        lnorm_k<<<BT, 128>>>(x, ln1_g + l*Cc, ln1_b + l*Cc, hh, hl);
        tgemm_k<false,false,false,true,false,true><<<gQKV, 256, TG_SMEM>>>(
            hh, hl, wqkv_h + (size_t)l*NQKV*Cc, wqkv_l + (size_t)l*NQKV*Cc,
            nullptr, nullptr, nullptr, qkvh, qkvl, nullptr, BT, NQKV, Cc);
        attn2_k<<<gattn, 128, ASMEM>>>(qkvh, qkvl, oh, ol);
        tgemm_k<true,false,true,false,false,true><<<g512, 256, TG_SMEM>>>(
            oh, ol, wo_h + (size_t)l*Cc*Cc, wo_l + (size_t)l*Cc*Cc,
            bo + l*Cc, x, x, nullptr, nullptr, nullptr, BT, Cc, Cc);
        lnorm_k<<<BT, 128>>>(x, ln2_g + l*Cc, ln2_b + l*Cc, hh, hl);
        tgemm_k<true,true,false,true,false,true><<<g2048, 256, TG_SMEM>>>(
            hh, hl, w1_h + (size_t)l*FFf*Cc, w1_l + (size_t)l*FFf*Cc,
            b1 + l*FFf, nullptr, nullptr, ffh, ffl, nullptr, BT, FFf, Cc);
        tgemm_k<true,false,true,false,false,true><<<g512, 256, TG_SMEM>>>(
            ffh, ffl, w2_h + (size_t)l*Cc*FFf, w2_l + (size_t)l*Cc*FFf,
            b2 + l*Cc, x, x, nullptr, nullptr, nullptr, BT, Cc, FFf);
    }
    lnorm_k<<<BT, 128>>>(x, lnf_g, lnf_b, hh, hl);
    // LM head: fp16x2 (BL=false, error lands directly on logits, ~2e-4) + fused expsum
    tgemm_k<true,false,false,false,true,false><<<gV, 256, TG_SMEM>>>(
        hh, hl, wlm_h, wlm_l, blm, nullptr, out, nullptr, nullptr, esum, BT, Vv, Cc);

    loss_final_k<<<BT/256, 256>>>(out, targets);
    int extra = out_size - (int)BTV;
    if (extra > 0) finalize_k<<<1, 128>>>(out, extra);
}

// round 16
// speedup vs baseline: 1.2530x; 1.0306x over previous
#include <cuda_runtime.h>
#include <cuda_fp16.h>
#include <cstdint>
#include <math.h>

// ---------------- problem constants ----------------
#define Vv 8192
#define Cc 512
#define Hh 16
#define HSs 32
#define Ll 12
#define FFf 2048
#define Bb 8
#define Tt 1024
#define BT (Bb*Tt)              // 8192
#define BTV ((size_t)BT * Vv)   // 67108864
#define NQKV 1536
#define X2_LAYER 10             // layers >= this use fp16x2 GEMMs

typedef unsigned int u32;
typedef unsigned long long u64;

// ---------------- scratch (device globals, no allocation) ----------------
__device__ float  g_x   [BT*Cc];     // residual stream, fp32
__device__ __half g_qkvh[BT*NQKV];   // qkv hi
__device__ __half g_qkvl[BT*NQKV];   // qkv lo
__device__ __half g_hh  [BT*Cc];
__device__ __half g_hl  [BT*Cc];
__device__ __half g_oh  [BT*Cc];
__device__ __half g_ol  [BT*Cc];
__device__ __half g_ffh [BT*FFf];
__device__ __half g_ffl [BT*FFf];
__device__ float  g_expsum[BT];
__device__ float  g_loss;

// split fp16 weights, [N][K] layout per layer
__device__ __half g_wqkv_h[Ll*NQKV*Cc];
__device__ __half g_wqkv_l[Ll*NQKV*Cc];
__device__ __half g_wo_h  [Ll*Cc*Cc];
__device__ __half g_wo_l  [Ll*Cc*Cc];
__device__ __half g_w1_h  [Ll*FFf*Cc];
__device__ __half g_w1_l  [Ll*FFf*Cc];
__device__ __half g_w2_h  [Ll*Cc*FFf];
__device__ __half g_w2_l  [Ll*Cc*FFf];
__device__ __half g_wlm_h [Vv*Cc];
__device__ __half g_wlm_l [Vv*Cc];

// ---------------- asm wrappers ----------------
__device__ __forceinline__ void mma_f16(float* d, const u32* a, const u32* b) {
    asm volatile("mma.sync.aligned.m16n8k16.row.col.f32.f16.f16.f32 "
        "{%0,%1,%2,%3}, {%4,%5,%6,%7}, {%8,%9}, {%0,%1,%2,%3};"
        : "+f"(d[0]), "+f"(d[1]), "+f"(d[2]), "+f"(d[3])
        : "r"(a[0]), "r"(a[1]), "r"(a[2]), "r"(a[3]),
          "r"(b[0]), "r"(b[1]));
}
__device__ __forceinline__ void ldsm4(u32* r, u32 addr) {
    asm volatile("ldmatrix.sync.aligned.m8n8.x4.shared.b16 "
        "{%0,%1,%2,%3}, [%4];"
        : "=r"(r[0]), "=r"(r[1]), "=r"(r[2]), "=r"(r[3]) : "r"(addr));
}
__device__ __forceinline__ void ldsm4t(u32* r, u32 addr) {
    asm volatile("ldmatrix.sync.aligned.m8n8.x4.trans.shared.b16 "
        "{%0,%1,%2,%3}, [%4];"
        : "=r"(r[0]), "=r"(r[1]), "=r"(r[2]), "=r"(r[3]) : "r"(addr));
}
__device__ __forceinline__ void cpa16(u32 dst, const void* src) {
    asm volatile("cp.async.cg.shared.global [%0], [%1], 16;" :: "r"(dst), "l"(src));
}
__device__ __forceinline__ void cp_commit() {
    asm volatile("cp.async.commit_group;" ::: "memory");
}
template<int N>
__device__ __forceinline__ void cp_wait() {
    asm volatile("cp.async.wait_group %0;" :: "n"(N) : "memory");
}
__device__ __forceinline__ u32 packh2(float x, float y) {
    __half2 h = __halves2half2(__float2half_rn(x), __float2half_rn(y));
    return *(u32*)&h;
}

// ---------------- fused weight prep ----------------
__device__ __forceinline__ void tsplit_tile(const float* __restrict__ src,
                                            __half* __restrict__ hi,
                                            __half* __restrict__ lo,
                                            int K, int N, int n0, int k0,
                                            float (*t)[33], int tx, int ty) {
    #pragma unroll
    for (int r = 0; r < 4; r++)
        t[ty + 8*r][tx] = src[(size_t)(k0 + ty + 8*r) * N + n0 + tx];
    __syncthreads();
    #pragma unroll
    for (int r = 0; r < 4; r++) {
        int n = ty + 8*r;
        float v = t[tx][n];
        __half vh = __float2half_rn(v);
        __half vl = __float2half_rn(v - __half2float(vh));
        size_t o = (size_t)(n0 + n) * K + k0 + tx;
        hi[o] = vh; lo[o] = vl;
    }
}

__global__ __launch_bounds__(256) void prep_k(const float* __restrict__ Wq,
                                              const float* __restrict__ Wk,
                                              const float* __restrict__ Wv,
                                              const float* __restrict__ Wo,
                                              const float* __restrict__ W1,
                                              const float* __restrict__ W2,
                                              const float* __restrict__ Wlm) {
    __shared__ float t[32][33];
    int b = blockIdx.x;
    int tx = threadIdx.x, ty = threadIdx.y;
    if (b < 3072) {
        int c0 = (b & 15) * 32, h = (b >> 4) & 15, l = b >> 8;
        const float* srcs[3] = {Wq, Wk, Wv};
        for (int s = 0; s < 3; s++) {
            const float* src = srcs[s] + ((size_t)(l*Hh + h) * Cc) * HSs;
            #pragma unroll
            for (int r = 0; r < 4; r++)
                t[ty + 8*r][tx] = src[(size_t)(c0 + ty + 8*r) * HSs + tx];
            __syncthreads();
            size_t nbase = (size_t)l * NQKV + s * 512 + h * 32;
            #pragma unroll
            for (int r = 0; r < 4; r++) {
                int d = ty + 8*r;
                float v = t[tx][d];
                __half hi = __float2half_rn(v);
                __half lo = __float2half_rn(v - __half2float(hi));
                size_t o = (nbase + d) * Cc + c0 + tx;
                g_wqkv_h[o] = hi; g_wqkv_l[o] = lo;
            }
            __syncthreads();
        }
    } else if (b < 6144) {
        b -= 3072;
        int l = b >> 8, n0 = (b & 15) * 32, k0 = ((b >> 4) & 15) * 32;
        tsplit_tile(Wo + (size_t)l*Cc*Cc, g_wo_h + (size_t)l*Cc*Cc, g_wo_l + (size_t)l*Cc*Cc,
                    Cc, Cc, n0, k0, t, tx, ty);
    } else if (b < 18432) {
        b -= 6144;
        int l = b >> 10, rem = b & 1023;
        int n0 = (rem & 63) * 32, k0 = (rem >> 6) * 32;
        tsplit_tile(W1 + (size_t)l*Cc*FFf, g_w1_h + (size_t)l*FFf*Cc, g_w1_l + (size_t)l*FFf*Cc,
                    Cc, FFf, n0, k0, t, tx, ty);
    } else if (b < 30720) {
        b -= 18432;
        int l = b >> 10, rem = b & 1023;
        int n0 = (rem & 15) * 32, k0 = (rem >> 4) * 32;
        tsplit_tile(W2 + (size_t)l*FFf*Cc, g_w2_h + (size_t)l*Cc*FFf, g_w2_l + (size_t)l*Cc*FFf,
                    FFf, Cc, n0, k0, t, tx, ty);
    } else {
        b -= 30720;
        int n0 = (b & 255) * 32, k0 = (b >> 8) * 32;
        tsplit_tile(Wlm, g_wlm_h, g_wlm_l, Cc, Vv, n0, k0, t, tx, ty);
    }
}

// ---------------- embedding (+ zero expsum/loss) ----------------
__global__ __launch_bounds__(128) void embed_k(const int* __restrict__ idx,
                                               const int* __restrict__ lab,
                                               const float* __restrict__ tok_emb,
                                               const float* __restrict__ lab_emb,
                                               const float* __restrict__ pos_emb) {
    int i = blockIdx.x;
    if (threadIdx.x == 0) {
        g_expsum[i] = 0.f;
        if (i == 0) g_loss = 0.f;
    }
    int t = i & (Tt-1);
    int ix = idx[i];
    int lb = lab[i];
    const float4* te = (const float4*)(tok_emb + (size_t)ix*Cc);
    const float4* le = (const float4*)(lab_emb + (size_t)lb*Cc);
    const float4* pe = (const float4*)(pos_emb + (size_t)t *Cc);
    float4* xo = (float4*)(g_x + (size_t)i*Cc);
    int c = threadIdx.x;
    float4 a = te[c], b = le[c], p = pe[c];
    xo[c] = make_float4(a.x+b.x+p.x, a.y+b.y+p.y, a.z+b.z+p.z, a.w+b.w+p.w);
}

// ---------------- layernorm: fp32 in -> fp16 hi/lo out ----------------
__global__ __launch_bounds__(128) void lnorm_k(const float* __restrict__ x,
                                               const float* __restrict__ g,
                                               const float* __restrict__ b,
                                               __half* __restrict__ yh,
                                               __half* __restrict__ yl) {
    int row = blockIdx.x;
    const float4* xr = (const float4*)(x + (size_t)row*Cc);
    float4 v = xr[threadIdx.x];
    float s  = v.x+v.y+v.z+v.w;
    float s2 = v.x*v.x + v.y*v.y + v.z*v.z + v.w*v.w;
    for (int o = 16; o > 0; o >>= 1) {
        s  += __shfl_down_sync(0xffffffff, s,  o);
        s2 += __shfl_down_sync(0xffffffff, s2, o);
    }
    __shared__ float sh[4], sh2[4];
    int wid = threadIdx.x >> 5, lane = threadIdx.x & 31;
    if (lane == 0) { sh[wid] = s; sh2[wid] = s2; }
    __syncthreads();
    __shared__ float smean, srstd;
    if (threadIdx.x == 0) {
        float ts = sh[0]+sh[1]+sh[2]+sh[3];
        float ts2 = sh2[0]+sh2[1]+sh2[2]+sh2[3];
        float mean = ts * (1.0f/Cc);
        float var = ts2 * (1.0f/Cc) - mean*mean;
        smean = mean;
        srstd = rsqrtf(var + 1e-5f);
    }
    __syncthreads();
    float mean = smean, rstd = srstd;
    int c = threadIdx.x * 4;
    float4 gg = *(const float4*)(g + c);
    float4 bb = *(const float4*)(b + c);
    float ov[4];
    ov[0] = (v.x-mean)*rstd*gg.x + bb.x;
    ov[1] = (v.y-mean)*rstd*gg.y + bb.y;
    ov[2] = (v.z-mean)*rstd*gg.z + bb.z;
    ov[3] = (v.w-mean)*rstd*gg.w + bb.w;
    __half hv[4], lv[4];
    #pragma unroll
    for (int e = 0; e < 4; e++) {
        hv[e] = __float2half_rn(ov[e]);
        lv[e] = __float2half_rn(ov[e] - __half2float(hv[e]));
    }
    *(uint2*)(yh + (size_t)row*Cc + c) = *(uint2*)hv;
    *(uint2*)(yl + (size_t)row*Cc + c) = *(uint2*)lv;
}

// ---------------- GEMM: fp16x3 on HMMA (BL=false -> fp16x2, no B-lo) ----------------
#define SAL_B 10240
#define SBH_B 20480
#define SBL_B 30720
#define STG_B 40960
#define TG_SMEM (2*STG_B)

template<bool BIAS, bool RELU, bool RES, bool SPLIT, bool EXPS, bool BL>
__global__ __launch_bounds__(256, 2) void tgemm_k(const __half* __restrict__ Ahg,
                                                  const __half* __restrict__ Alg,
                                                  const __half* __restrict__ Bhg,
                                                  const __half* __restrict__ Blg,
                                                  const float* __restrict__ bias,
                                                  const float* __restrict__ res,
                                                  float* __restrict__ Cf,
                                                  __half* __restrict__ Ch,
                                                  __half* __restrict__ Cl,
                                                  float* __restrict__ expsum,
                                                  int M, int N, int K) {
    extern __shared__ __half smd[];
    const int tid = threadIdx.x;
    const int lane = tid & 31, w = tid >> 5;
    const int row0 = blockIdx.y * 128, col0 = blockIdx.x * 128;
    const int m0w = (w >> 2) * 64, n0w = (w & 3) * 32;
    const u32 sb = (u32)__cvta_generic_to_shared(smd);

    float acc[4][4][4];
    #pragma unroll
    for (int i = 0; i < 4; i++)
        #pragma unroll
        for (int j = 0; j < 4; j++)
            #pragma unroll
            for (int e = 0; e < 4; e++) acc[i][j][e] = 0.f;

    const int nk = K >> 5;
    const int r = tid >> 1;
    const int hofs = (tid & 1) << 4;
    const __half* aHp = Ahg + (size_t)(row0 + r) * K + hofs;
    const __half* aLp = Alg + (size_t)(row0 + r) * K + hofs;
    const __half* bHp = Bhg + (size_t)(col0 + r) * K + hofs;
    const __half* bLp = BL ? (Blg + (size_t)(col0 + r) * K + hofs) : nullptr;
    const u32 dstA = sb + (u32)(r * 80 + hofs * 2);

    #define TG_ISSUE(bufbyte, kc) do {                                   \
        int _ko = (kc) << 5;                                             \
        u32 _d = dstA + (bufbyte);                                       \
        cpa16(_d,                 aHp + _ko);                            \
        cpa16(_d + 16,            aHp + _ko + 8);                        \
        cpa16(_d + SAL_B,         aLp + _ko);                            \
        cpa16(_d + SAL_B + 16,    aLp + _ko + 8);                        \
        cpa16(_d + SBH_B,         bHp + _ko);                            \
        cpa16(_d + SBH_B + 16,    bHp + _ko + 8);                        \
        if (BL) {                                                        \
            cpa16(_d + SBL_B,         bLp + _ko);                        \
            cpa16(_d + SBL_B + 16,    bLp + _ko + 8);                    \
        }                                                                \
    } while (0)

    TG_ISSUE(0, 0);
    cp_commit();

    const int lr = lane & 7, lg1 = (lane >> 3) & 1, lg2 = lane >> 4;

    for (int kt = 0; kt < nk; kt++) {
        const u32 cur = (u32)((kt & 1) * STG_B);
        cp_wait<0>();
        __syncthreads();
        if (kt + 1 < nk) {
            TG_ISSUE((u32)(((kt + 1) & 1) * STG_B), kt + 1);
            cp_commit();
        }

        #pragma unroll
        for (int ks = 0; ks < 32; ks += 16) {
            u32 afh[4][4], afl[4][4];
            #pragma unroll
            for (int mi = 0; mi < 4; mi++) {
                int row = m0w + mi*16 + lr + lg1*8;
                u32 ad = sb + cur + (u32)((row*40 + ks + lg2*8) * 2);
                ldsm4(afh[mi], ad);
                ldsm4(afl[mi], ad + SAL_B);
            }
            u32 bfh[4][2], bfl[4][2];
            #pragma unroll
            for (int bi = 0; bi < 2; bi++) {
                int n = n0w + bi*16 + lr + lg2*8;
                u32 bd = sb + cur + SBH_B + (u32)((n*40 + ks + lg1*8) * 2);
                u32 t1[4];
                ldsm4(t1, bd);
                bfh[2*bi][0]   = t1[0]; bfh[2*bi][1]   = t1[1];
                bfh[2*bi+1][0] = t1[2]; bfh[2*bi+1][1] = t1[3];
                if (BL) {
                    u32 t2[4];
                    ldsm4(t2, bd + (SBL_B - SBH_B));
                    bfl[2*bi][0]   = t2[0]; bfl[2*bi][1]   = t2[1];
                    bfl[2*bi+1][0] = t2[2]; bfl[2*bi+1][1] = t2[3];
                }
            }
            #pragma unroll
            for (int mi = 0; mi < 4; mi++)
                #pragma unroll
                for (int ni = 0; ni < 4; ni++) {
                    mma_f16(acc[mi][ni], afh[mi], bfh[ni]);
                    if (BL) mma_f16(acc[mi][ni], afh[mi], bfl[ni]);
                    mma_f16(acc[mi][ni], afl[mi], bfh[ni]);
                }
        }
    }
    #undef TG_ISSUE

    #pragma unroll
    for (int mi = 0; mi < 4; mi++) {
        int r0 = row0 + m0w + mi*16 + (lane >> 2);
        float es0 = 0.f, es1 = 0.f;
        #pragma unroll
        for (int ni = 0; ni < 4; ni++) {
            int cc = col0 + n0w + ni*8 + (lane & 3)*2;
            float2 v0 = make_float2(acc[mi][ni][0], acc[mi][ni][1]);
            float2 v1 = make_float2(acc[mi][ni][2], acc[mi][ni][3]);
            if (BIAS) {
                float2 bb = *(const float2*)(bias + cc);
                v0.x += bb.x; v0.y += bb.y; v1.x += bb.x; v1.y += bb.y;
            }
            if (RELU) {
                v0.x = fmaxf(v0.x, 0.f); v0.y = fmaxf(v0.y, 0.f);
                v1.x = fmaxf(v1.x, 0.f); v1.y = fmaxf(v1.y, 0.f);
            }
            if (RES) {
                float2 ra = *(const float2*)(res + (size_t)r0*N + cc);
                float2 rb = *(const float2*)(res + (size_t)(r0+8)*N + cc);
                v0.x += ra.x; v0.y += ra.y; v1.x += rb.x; v1.y += rb.y;
            }
            if (SPLIT) {
                __half h0 = __float2half_rn(v0.x), h1 = __float2half_rn(v0.y);
                __half h2 = __float2half_rn(v1.x), h3 = __float2half_rn(v1.y);
                __half l0 = __float2half_rn(v0.x - __half2float(h0));
                __half l1 = __float2half_rn(v0.y - __half2float(h1));
                __half l2 = __float2half_rn(v1.x - __half2float(h2));
                __half l3 = __float2half_rn(v1.y - __half2float(h3));
                *(__half2*)(Ch + (size_t)r0*N + cc)     = __halves2half2(h0, h1);
                *(__half2*)(Ch + (size_t)(r0+8)*N + cc) = __halves2half2(h2, h3);
                *(__half2*)(Cl + (size_t)r0*N + cc)     = __halves2half2(l0, l1);
                *(__half2*)(Cl + (size_t)(r0+8)*N + cc) = __halves2half2(l2, l3);
            } else {
                *(float2*)(Cf + (size_t)r0*N + cc) = v0;
                *(float2*)(Cf + (size_t)(r0+8)*N + cc) = v1;
            }
            if (EXPS) {
                es0 += __expf(v0.x) + __expf(v0.y);
                es1 += __expf(v1.x) + __expf(v1.y);
            }
        }
        if (EXPS) {
            es0 += __shfl_xor_sync(0xffffffffu, es0, 1);
            es0 += __shfl_xor_sync(0xffffffffu, es0, 2);
            es1 += __shfl_xor_sync(0xffffffffu, es1, 1);
            es1 += __shfl_xor_sync(0xffffffffu, es1, 2);
            if ((lane & 3) == 0) {
                atomicAdd(&expsum[r0], es0);
                atomicAdd(&expsum[r0 + 8], es1);
            }
        }
    }
}

// ---------------- tensor-core causal flash attention ----------------
#define AP 40
#define ASMEM (25600*2)

__global__ __launch_bounds__(128) void attn2_k(const __half* __restrict__ qkvh,
                                               const __half* __restrict__ qkvl,
                                               __half* __restrict__ ohg,
                                               __half* __restrict__ olg) {
    extern __shared__ __half ash[];
    const u32 sb = (u32)__cvta_generic_to_shared(ash);
    const int tid = threadIdx.x;
    const int l = tid & 31, w = tid >> 5;
    const int bh = blockIdx.y, b = bh >> 4, h = bh & 15;
    const int qt = (int)gridDim.x - 1 - (int)blockIdx.x;
    const float scale = 0.17677669529663689f;

    const int tb = b*Tt + qt*64;
    const int rr = tid >> 1;
    const int ss = tid & 1;

    {
        const __half* qh = qkvh + (size_t)(tb + rr)*NQKV + h*HSs + ss*16;
        const __half* ql = qkvl + (size_t)(tb + rr)*NQKV + h*HSs + ss*16;
        u32 d = sb + (u32)((rr*AP + ss*16) * 2);
        cpa16(d, qh);              cpa16(d + 16, qh + 8);
        cpa16(d + 2560*2, ql);     cpa16(d + 2560*2 + 16, ql + 8);
    }
    #define AT_ISSUE(stgh, kt) do {                                          \
        int _tok = b*Tt + (kt)*64 + rr;                                      \
        const __half* _kh = qkvh + (size_t)_tok*NQKV + 512  + h*HSs + ss*16; \
        const __half* _kl = qkvl + (size_t)_tok*NQKV + 512  + h*HSs + ss*16; \
        const __half* _vh = qkvh + (size_t)_tok*NQKV + 1024 + h*HSs + ss*16; \
        const __half* _vl = qkvl + (size_t)_tok*NQKV + 1024 + h*HSs + ss*16; \
        u32 _d = sb + (u32)(((stgh) + rr*AP + ss*16) * 2);                   \
        cpa16(_d, _kh);               cpa16(_d + 16, _kh + 8);               \
        cpa16(_d + 2560*2, _kl);      cpa16(_d + 2560*2 + 16, _kl + 8);      \
        cpa16(_d + 5120*2, _vh);      cpa16(_d + 5120*2 + 16, _vh + 8);      \
        cpa16(_d + 7680*2, _vl);      cpa16(_d + 7680*2 + 16, _vl + 8);      \
    } while (0)

    AT_ISSUE(5120, 0);
    cp_commit();

    const int lr = l & 7, lg1 = (l >> 3) & 1, lg2 = l >> 4;
    const int g = l >> 2;
    const int cq = (l & 3) * 2;

    u32 qah[2][4], qal[2][4];
    float m0 = -1e30f, m1 = -1e30f, sum0 = 0.f, sum1 = 0.f;
    float oacc[4][4];
    #pragma unroll
    for (int i = 0; i < 4; i++)
        #pragma unroll
        for (int e = 0; e < 4; e++) oacc[i][e] = 0.f;

    for (int kt = 0; kt <= qt; kt++) {
        const u32 stg = (u32)(5120 + (kt & 1) * 10240);
        cp_wait<0>();
        __syncthreads();
        if (kt < qt) { AT_ISSUE((u32)(5120 + ((kt+1) & 1) * 10240), kt + 1); cp_commit(); }
        if (kt == 0) {
            #pragma unroll
            for (int ks = 0; ks < 2; ks++) {
                int row = w*16 + lr + lg1*8;
                u32 ad = sb + (u32)((row*AP + ks*16 + lg2*8) * 2);
                ldsm4(qah[ks], ad);
                ldsm4(qal[ks], ad + 2560*2);
            }
        }

        float sc[8][4];
        #pragma unroll
        for (int nt = 0; nt < 8; nt++)
            #pragma unroll
            for (int e = 0; e < 4; e++) sc[nt][e] = 0.f;

        #pragma unroll
        for (int ks = 0; ks < 2; ks++) {
            u32 kbh[8][2], kbl[8][2];
            #pragma unroll
            for (int bi = 0; bi < 4; bi++) {
                int n = bi*16 + lr + lg2*8;
                u32 bd = sb + (u32)((stg + n*AP + ks*16 + lg1*8) * 2);
                u32 t1[4], t2[4];
                ldsm4(t1, bd);
                ldsm4(t2, bd + 2560*2);
                kbh[2*bi][0]   = t1[0]; kbh[2*bi][1]   = t1[1];
                kbh[2*bi+1][0] = t1[2]; kbh[2*bi+1][1] = t1[3];
                kbl[2*bi][0]   = t2[0]; kbl[2*bi][1]   = t2[1];
                kbl[2*bi+1][0] = t2[2]; kbl[2*bi+1][1] = t2[3];
            }
            #pragma unroll
            for (int nt = 0; nt < 8; nt++) {
                mma_f16(sc[nt], qah[ks], kbh[nt]);
                mma_f16(sc[nt], qah[ks], kbl[nt]);
                mma_f16(sc[nt], qal[ks], kbh[nt]);
            }
        }

        if (kt == qt) {
            int r0 = w*16 + g, r1 = r0 + 8;
            #pragma unroll
            for (int nt = 0; nt < 8; nt++) {
                int c0 = nt*8 + cq, c1 = c0 + 1;
                if (c0 > r0) sc[nt][0] = -1e30f;
                if (c1 > r0) sc[nt][1] = -1e30f;
                if (c0 > r1) sc[nt][2] = -1e30f;
                if (c1 > r1) sc[nt][3] = -1e30f;
            }
        }

        float t0 = -1e30f, t1 = -1e30f;
        #pragma unroll
        for (int nt = 0; nt < 8; nt++) {
            t0 = fmaxf(t0, fmaxf(sc[nt][0], sc[nt][1]));
            t1 = fmaxf(t1, fmaxf(sc[nt][2], sc[nt][3]));
        }
        t0 = fmaxf(t0, __shfl_xor_sync(0xffffffffu, t0, 1));
        t0 = fmaxf(t0, __shfl_xor_sync(0xffffffffu, t0, 2));
        t1 = fmaxf(t1, __shfl_xor_sync(0xffffffffu, t1, 1));
        t1 = fmaxf(t1, __shfl_xor_sync(0xffffffffu, t1, 2));
        float mn0 = fmaxf(m0, t0), mn1 = fmaxf(m1, t1);
        float cor0 = __expf((m0 - mn0) * scale);
        float cor1 = __expf((m1 - mn1) * scale);
        sum0 *= cor0; sum1 *= cor1;
        #pragma unroll
        for (int nt = 0; nt < 4; nt++) {
            oacc[nt][0] *= cor0; oacc[nt][1] *= cor0;
            oacc[nt][2] *= cor1; oacc[nt][3] *= cor1;
        }
        m0 = mn0; m1 = mn1;

        #pragma unroll
        for (int j = 0; j < 4; j++) {
            float p00 = __expf((sc[2*j][0]   - m0) * scale);
            float p01 = __expf((sc[2*j][1]   - m0) * scale);
            float p02 = __expf((sc[2*j][2]   - m1) * scale);
            float p03 = __expf((sc[2*j][3]   - m1) * scale);
            float p10 = __expf((sc[2*j+1][0] - m0) * scale);
            float p11 = __expf((sc[2*j+1][1] - m0) * scale);
            float p12 = __expf((sc[2*j+1][2] - m1) * scale);
            float p13 = __expf((sc[2*j+1][3] - m1) * scale);
            sum0 += p00 + p01 + p10 + p11;
            sum1 += p02 + p03 + p12 + p13;

            u32 pah[4], pal[4];
            pah[0] = packh2(p00, p01);
            pah[1] = packh2(p02, p03);
            pah[2] = packh2(p10, p11);
            pah[3] = packh2(p12, p13);
            {
                __half2* hp;
                hp = (__half2*)&pah[0];
                pal[0] = packh2(p00 - __half2float(__low2half(*hp)), p01 - __half2float(__high2half(*hp)));
                hp = (__half2*)&pah[1];
                pal[1] = packh2(p02 - __half2float(__low2half(*hp)), p03 - __half2float(__high2half(*hp)));
                hp = (__half2*)&pah[2];
                pal[2] = packh2(p10 - __half2float(__low2half(*hp)), p11 - __half2float(__high2half(*hp)));
                hp = (__half2*)&pah[3];
                pal[3] = packh2(p12 - __half2float(__low2half(*hp)), p13 - __half2float(__high2half(*hp)));
            }

            u32 vbh[4][2], vbl[4][2];
            #pragma unroll
            for (int vp = 0; vp < 2; vp++) {
                int krow = j*16 + (l & 7) + ((l >> 3) & 1) * 8;
                int ncol = vp*16 + (l >> 4) * 8;
                u32 vd = sb + (u32)((stg + 5120 + krow*AP + ncol) * 2);
                u32 t1r[4], t2r[4];
                ldsm4t(t1r, vd);
                ldsm4t(t2r, vd + 2560*2);
                vbh[2*vp][0]   = t1r[0]; vbh[2*vp][1]   = t1r[1];
                vbh[2*vp+1][0] = t1r[2]; vbh[2*vp+1][1] = t1r[3];
                vbl[2*vp][0]   = t2r[0]; vbl[2*vp][1]   = t2r[1];
                vbl[2*vp+1][0] = t2r[2]; vbl[2*vp+1][1] = t2r[3];
            }
            #pragma unroll
            for (int nt = 0; nt < 4; nt++) {
                mma_f16(oacc[nt], pah, vbh[nt]);
                mma_f16(oacc[nt], pah, vbl[nt]);
                mma_f16(oacc[nt], pal, vbh[nt]);
            }
        }
    }
    #undef AT_ISSUE

    sum0 += __shfl_xor_sync(0xffffffffu, sum0, 1);
    sum0 += __shfl_xor_sync(0xffffffffu, sum0, 2);
    sum1 += __shfl_xor_sync(0xffffffffu, sum1, 1);
    sum1 += __shfl_xor_sync(0xffffffffu, sum1, 2);
    float i0 = 1.f / sum0, i1 = 1.f / sum1;
    int tok0 = tb + w*16 + g;
    #pragma unroll
    for (int nt = 0; nt < 4; nt++) {
        int ch = h*HSs + nt*8 + cq;
        float v0 = oacc[nt][0]*i0, v1 = oacc[nt][1]*i0;
        float v2 = oacc[nt][2]*i1, v3 = oacc[nt][3]*i1;
        __half h0 = __float2half_rn(v0), h1 = __float2half_rn(v1);
        __half h2 = __float2half_rn(v2), h3 = __float2half_rn(v3);
        __half l0 = __float2half_rn(v0 - __half2float(h0));
        __half l1 = __float2half_rn(v1 - __half2float(h1));
        __half l2 = __float2half_rn(v2 - __half2float(h2));
        __half l3 = __float2half_rn(v3 - __half2float(h3));
        *(__half2*)(ohg + (size_t)tok0*Cc + ch)     = __halves2half2(h0, h1);
        *(__half2*)(ohg + (size_t)(tok0+8)*Cc + ch) = __halves2half2(h2, h3);
        *(__half2*)(olg + (size_t)tok0*Cc + ch)     = __halves2half2(l0, l1);
        *(__half2*)(olg + (size_t)(tok0+8)*Cc + ch) = __halves2half2(l2, l3);
    }
}

// ---------------- loss (fused path) ----------------
__global__ __launch_bounds__(256) void loss_final_k(const float* __restrict__ logits,
                                                    const int* __restrict__ targets) {
    int row = blockIdx.x * 256 + threadIdx.x;
    float lp = logits[(size_t)row * Vv + targets[row]] - logf(g_expsum[row]);
    for (int o = 16; o > 0; o >>= 1) lp += __shfl_down_sync(0xffffffff, lp, o);
    if ((threadIdx.x & 31) == 0) atomicAdd(&g_loss, lp);
}

__global__ void finalize_k(float* out, int extra) {
    float lv = -g_loss / (float)BT;
    for (int i = threadIdx.x + blockIdx.x*blockDim.x; i < extra; i += blockDim.x*gridDim.x)
        out[BTV + i] = lv;
}

// ---------------- host launcher ----------------
static void* symaddr(const void* sym) {
    void* p = nullptr;
    cudaGetSymbolAddress(&p, sym);
    return p;
}

extern "C" void kernel_launch(void* const* d_in, const int* in_sizes, int n_in,
                              void* d_out, int out_size) {
    const int*   idx      = (const int*)  d_in[0];
    const int*   idx_lab  = (const int*)  d_in[1];
    const int*   targets  = (const int*)  d_in[2];
    const float* tok_emb  = (const float*)d_in[3];
    const float* pos_emb  = (const float*)d_in[4];
    const float* lab_emb  = (const float*)d_in[5];
    const float* Wq       = (const float*)d_in[6];
    const float* Wk       = (const float*)d_in[7];
    const float* Wv       = (const float*)d_in[8];
    const float* Wo       = (const float*)d_in[9];
    const float* bo       = (const float*)d_in[10];
    const float* ln1_g    = (const float*)d_in[11];
    const float* ln1_b    = (const float*)d_in[12];
    const float* W1       = (const float*)d_in[13];
    const float* b1       = (const float*)d_in[14];
    const float* W2       = (const float*)d_in[15];
    const float* b2       = (const float*)d_in[16];
    const float* ln2_g    = (const float*)d_in[17];
    const float* ln2_b    = (const float*)d_in[18];
    const float* lnf_g    = (const float*)d_in[19];
    const float* lnf_b    = (const float*)d_in[20];
    const float* Wlm      = (const float*)d_in[21];
    const float* blm      = (const float*)d_in[22];
    float* out = (float*)d_out;

    float*  x    = (float*) symaddr(g_x);
    __half* qkvh = (__half*)symaddr(g_qkvh);
    __half* qkvl = (__half*)symaddr(g_qkvl);
    __half* hh   = (__half*)symaddr(g_hh);
    __half* hl   = (__half*)symaddr(g_hl);
    __half* oh   = (__half*)symaddr(g_oh);
    __half* ol   = (__half*)symaddr(g_ol);
    __half* ffh  = (__half*)symaddr(g_ffh);
    __half* ffl  = (__half*)symaddr(g_ffl);
    float*  esum = (float*) symaddr(g_expsum);
    __half* wqkv_h = (__half*)symaddr(g_wqkv_h);
    __half* wqkv_l = (__half*)symaddr(g_wqkv_l);
    __half* wo_h   = (__half*)symaddr(g_wo_h);
    __half* wo_l   = (__half*)symaddr(g_wo_l);
    __half* w1_h   = (__half*)symaddr(g_w1_h);
    __half* w1_l   = (__half*)symaddr(g_w1_l);
    __half* w2_h   = (__half*)symaddr(g_w2_h);
    __half* w2_l   = (__half*)symaddr(g_w2_l);
    __half* wlm_h  = (__half*)symaddr(g_wlm_h);
    __half* wlm_l  = (__half*)symaddr(g_wlm_l);

    cudaFuncSetAttribute(tgemm_k<false,false,false,true,false,true>,  cudaFuncAttributeMaxDynamicSharedMemorySize, TG_SMEM);
    cudaFuncSetAttribute(tgemm_k<true,false,true,false,false,true>,   cudaFuncAttributeMaxDynamicSharedMemorySize, TG_SMEM);
    cudaFuncSetAttribute(tgemm_k<true,true,false,true,false,true>,    cudaFuncAttributeMaxDynamicSharedMemorySize, TG_SMEM);
    cudaFuncSetAttribute(tgemm_k<false,false,false,true,false,false>, cudaFuncAttributeMaxDynamicSharedMemorySize, TG_SMEM);
    cudaFuncSetAttribute(tgemm_k<true,false,true,false,false,false>,  cudaFuncAttributeMaxDynamicSharedMemorySize, TG_SMEM);
    cudaFuncSetAttribute(tgemm_k<true,true,false,true,false,false>,   cudaFuncAttributeMaxDynamicSharedMemorySize, TG_SMEM);
    cudaFuncSetAttribute(tgemm_k<true,false,false,false,true,false>,  cudaFuncAttributeMaxDynamicSharedMemorySize, TG_SMEM);
    cudaFuncSetAttribute(attn2_k, cudaFuncAttributeMaxDynamicSharedMemorySize, ASMEM);

    prep_k<<<34816, dim3(32, 8)>>>(Wq, Wk, Wv, Wo, W1, W2, Wlm);
    embed_k<<<BT, 128>>>(idx, idx_lab, tok_emb, lab_emb, pos_emb);

    dim3 gQKV(NQKV/128, BT/128);   // (12, 64)
    dim3 g512(Cc/128,   BT/128);   // (4, 64)
    dim3 g2048(FFf/128, BT/128);   // (16, 64)
    dim3 gV(Vv/128,     BT/128);   // (64, 64)
    dim3 gattn(Tt/64, Bb*Hh);      // (16, 128)

    for (int l = 0; l < Ll; l++) {
        const bool x3 = (l < X2_LAYER);
        lnorm_k<<<BT, 128>>>(x, ln1_g + l*Cc, ln1_b + l*Cc, hh, hl);
        if (x3)
            tgemm_k<false,false,false,true,false,true><<<gQKV, 256, TG_SMEM>>>(
                hh, hl, wqkv_h + (size_t)l*NQKV*Cc, wqkv_l + (size_t)l*NQKV*Cc,
                nullptr, nullptr, nullptr, qkvh, qkvl, nullptr, BT, NQKV, Cc);
        else
            tgemm_k<false,false,false,true,false,false><<<gQKV, 256, TG_SMEM>>>(
                hh, hl, wqkv_h + (size_t)l*NQKV*Cc, wqkv_l + (size_t)l*NQKV*Cc,
                nullptr, nullptr, nullptr, qkvh, qkvl, nullptr, BT, NQKV, Cc);
        attn2_k<<<gattn, 128, ASMEM>>>(qkvh, qkvl, oh, ol);
        if (x3)
            tgemm_k<true,false,true,false,false,true><<<g512, 256, TG_SMEM>>>(
                oh, ol, wo_h + (size_t)l*Cc*Cc, wo_l + (size_t)l*Cc*Cc,
                bo + l*Cc, x, x, nullptr, nullptr, nullptr, BT, Cc, Cc);
        else
            tgemm_k<true,false,true,false,false,false><<<g512, 256, TG_SMEM>>>(
                oh, ol, wo_h + (size_t)l*Cc*Cc, wo_l + (size_t)l*Cc*Cc,
                bo + l*Cc, x, x, nullptr, nullptr, nullptr, BT, Cc, Cc);
        lnorm_k<<<BT, 128>>>(x, ln2_g + l*Cc, ln2_b + l*Cc, hh, hl);
        if (x3)
            tgemm_k<true,true,false,true,false,true><<<g2048, 256, TG_SMEM>>>(
                hh, hl, w1_h + (size_t)l*FFf*Cc, w1_l + (size_t)l*FFf*Cc,
                b1 + l*FFf, nullptr, nullptr, ffh, ffl, nullptr, BT, FFf, Cc);
        else
            tgemm_k<true,true,false,true,false,false><<<g2048, 256, TG_SMEM>>>(
                hh, hl, w1_h + (size_t)l*FFf*Cc, w1_l + (size_t)l*FFf*Cc,
                b1 + l*FFf, nullptr, nullptr, ffh, ffl, nullptr, BT, FFf, Cc);
        if (x3)
            tgemm_k<true,false,true,false,false,true><<<g512, 256, TG_SMEM>>>(
                ffh, ffl, w2_h + (size_t)l*Cc*FFf, w2_l + (size_t)l*Cc*FFf,
                b2 + l*Cc, x, x, nullptr, nullptr, nullptr, BT, Cc, FFf);
        else
            tgemm_k<true,false,true,false,false,false><<<g512, 256, TG_SMEM>>>(
                ffh, ffl, w2_h + (size_t)l*Cc*FFf, w2_l + (size_t)l*Cc*FFf,
                b2 + l*Cc, x, x, nullptr, nullptr, nullptr, BT, Cc, FFf);
    }
    lnorm_k<<<BT, 128>>>(x, lnf_g, lnf_b, hh, hl);
    // LM head: fp16x2 + fused expsum
    tgemm_k<true,false,false,false,true,false><<<gV, 256, TG_SMEM>>>(
        hh, hl, wlm_h, wlm_l, blm, nullptr, out, nullptr, nullptr, esum, BT, Vv, Cc);

    loss_final_k<<<BT/256, 256>>>(out, targets);
    int extra = out_size - (int)BTV;
    if (extra > 0) finalize_k<<<1, 128>>>(out, extra);
}

// round 17
// speedup vs baseline: 1.3837x; 1.1043x over previous
#include <cuda_runtime.h>
#include <cuda_fp16.h>
#include <cstdint>
#include <math.h>

// ---------------- problem constants ----------------
#define Vv 8192
#define Cc 512
#define Hh 16
#define HSs 32
#define Ll 12
#define FFf 2048
#define Bb 8
#define Tt 1024
#define BT (Bb*Tt)              // 8192
#define BTV ((size_t)BT * Vv)   // 67108864
#define NQKV 1536
#define X2_LAYER 4              // layers >= this use fp16x2 GEMMs

typedef unsigned int u32;
typedef unsigned long long u64;

// ---------------- scratch (device globals, no allocation) ----------------
__device__ float  g_x   [BT*Cc];     // residual stream, fp32
__device__ __half g_qkvh[BT*NQKV];   // qkv hi
__device__ __half g_qkvl[BT*NQKV];   // qkv lo
__device__ __half g_hh  [BT*Cc];
__device__ __half g_hl  [BT*Cc];
__device__ __half g_oh  [BT*Cc];
__device__ __half g_ol  [BT*Cc];
__device__ __half g_ffh [BT*FFf];
__device__ __half g_ffl [BT*FFf];
__device__ float  g_expsum[BT];
__device__ float  g_loss;

// split fp16 weights, [N][K] layout per layer
__device__ __half g_wqkv_h[Ll*NQKV*Cc];
__device__ __half g_wqkv_l[Ll*NQKV*Cc];
__device__ __half g_wo_h  [Ll*Cc*Cc];
__device__ __half g_wo_l  [Ll*Cc*Cc];
__device__ __half g_w1_h  [Ll*FFf*Cc];
__device__ __half g_w1_l  [Ll*FFf*Cc];
__device__ __half g_w2_h  [Ll*Cc*FFf];
__device__ __half g_w2_l  [Ll*Cc*FFf];
__device__ __half g_wlm_h [Vv*Cc];
__device__ __half g_wlm_l [Vv*Cc];

// ---------------- asm wrappers ----------------
__device__ __forceinline__ void mma_f16(float* d, const u32* a, const u32* b) {
    asm volatile("mma.sync.aligned.m16n8k16.row.col.f32.f16.f16.f32 "
        "{%0,%1,%2,%3}, {%4,%5,%6,%7}, {%8,%9}, {%0,%1,%2,%3};"
        : "+f"(d[0]), "+f"(d[1]), "+f"(d[2]), "+f"(d[3])
        : "r"(a[0]), "r"(a[1]), "r"(a[2]), "r"(a[3]),
          "r"(b[0]), "r"(b[1]));
}
__device__ __forceinline__ void ldsm4(u32* r, u32 addr) {
    asm volatile("ldmatrix.sync.aligned.m8n8.x4.shared.b16 "
        "{%0,%1,%2,%3}, [%4];"
        : "=r"(r[0]), "=r"(r[1]), "=r"(r[2]), "=r"(r[3]) : "r"(addr));
}
__device__ __forceinline__ void ldsm4t(u32* r, u32 addr) {
    asm volatile("ldmatrix.sync.aligned.m8n8.x4.trans.shared.b16 "
        "{%0,%1,%2,%3}, [%4];"
        : "=r"(r[0]), "=r"(r[1]), "=r"(r[2]), "=r"(r[3]) : "r"(addr));
}
__device__ __forceinline__ void cpa16(u32 dst, const void* src) {
    asm volatile("cp.async.cg.shared.global [%0], [%1], 16;" :: "r"(dst), "l"(src));
}
__device__ __forceinline__ void cp_commit() {
    asm volatile("cp.async.commit_group;" ::: "memory");
}
template<int N>
__device__ __forceinline__ void cp_wait() {
    asm volatile("cp.async.wait_group %0;" :: "n"(N) : "memory");
}
__device__ __forceinline__ u32 packh2(float x, float y) {
    __half2 h = __halves2half2(__float2half_rn(x), __float2half_rn(y));
    return *(u32*)&h;
}

// ---------------- fused weight prep ----------------
__device__ __forceinline__ void tsplit_tile(const float* __restrict__ src,
                                            __half* __restrict__ hi,
                                            __half* __restrict__ lo,
                                            int K, int N, int n0, int k0,
                                            float (*t)[33], int tx, int ty) {
    #pragma unroll
    for (int r = 0; r < 4; r++)
        t[ty + 8*r][tx] = src[(size_t)(k0 + ty + 8*r) * N + n0 + tx];
    __syncthreads();
    #pragma unroll
    for (int r = 0; r < 4; r++) {
        int n = ty + 8*r;
        float v = t[tx][n];
        __half vh = __float2half_rn(v);
        __half vl = __float2half_rn(v - __half2float(vh));
        size_t o = (size_t)(n0 + n) * K + k0 + tx;
        hi[o] = vh; lo[o] = vl;
    }
}

__global__ __launch_bounds__(256) void prep_k(const float* __restrict__ Wq,
                                              const float* __restrict__ Wk,
                                              const float* __restrict__ Wv,
                                              const float* __restrict__ Wo,
                                              const float* __restrict__ W1,
                                              const float* __restrict__ W2,
                                              const float* __restrict__ Wlm) {
    __shared__ float t[32][33];
    int b = blockIdx.x;
    int tx = threadIdx.x, ty = threadIdx.y;
    if (b < 3072) {
        int c0 = (b & 15) * 32, h = (b >> 4) & 15, l = b >> 8;
        const float* srcs[3] = {Wq, Wk, Wv};
        for (int s = 0; s < 3; s++) {
            const float* src = srcs[s] + ((size_t)(l*Hh + h) * Cc) * HSs;
            #pragma unroll
            for (int r = 0; r < 4; r++)
                t[ty + 8*r][tx] = src[(size_t)(c0 + ty + 8*r) * HSs + tx];
            __syncthreads();
            size_t nbase = (size_t)l * NQKV + s * 512 + h * 32;
            #pragma unroll
            for (int r = 0; r < 4; r++) {
                int d = ty + 8*r;
                float v = t[tx][d];
                __half hi = __float2half_rn(v);
                __half lo = __float2half_rn(v - __half2float(hi));
                size_t o = (nbase + d) * Cc + c0 + tx;
                g_wqkv_h[o] = hi; g_wqkv_l[o] = lo;
            }
            __syncthreads();
        }
    } else if (b < 6144) {
        b -= 3072;
        int l = b >> 8, n0 = (b & 15) * 32, k0 = ((b >> 4) & 15) * 32;
        tsplit_tile(Wo + (size_t)l*Cc*Cc, g_wo_h + (size_t)l*Cc*Cc, g_wo_l + (size_t)l*Cc*Cc,
                    Cc, Cc, n0, k0, t, tx, ty);
    } else if (b < 18432) {
        b -= 6144;
        int l = b >> 10, rem = b & 1023;
        int n0 = (rem & 63) * 32, k0 = (rem >> 6) * 32;
        tsplit_tile(W1 + (size_t)l*Cc*FFf, g_w1_h + (size_t)l*FFf*Cc, g_w1_l + (size_t)l*FFf*Cc,
                    Cc, FFf, n0, k0, t, tx, ty);
    } else if (b < 30720) {
        b -= 18432;
        int l = b >> 10, rem = b & 1023;
        int n0 = (rem & 15) * 32, k0 = (rem >> 4) * 32;
        tsplit_tile(W2 + (size_t)l*FFf*Cc, g_w2_h + (size_t)l*Cc*FFf, g_w2_l + (size_t)l*Cc*FFf,
                    FFf, Cc, n0, k0, t, tx, ty);
    } else {
        b -= 30720;
        int n0 = (b & 255) * 32, k0 = (b >> 8) * 32;
        tsplit_tile(Wlm, g_wlm_h, g_wlm_l, Cc, Vv, n0, k0, t, tx, ty);
    }
}

// ---------------- embedding (+ zero expsum/loss) ----------------
__global__ __launch_bounds__(128) void embed_k(const int* __restrict__ idx,
                                               const int* __restrict__ lab,
                                               const float* __restrict__ tok_emb,
                                               const float* __restrict__ lab_emb,
                                               const float* __restrict__ pos_emb) {
    int i = blockIdx.x;
    if (threadIdx.x == 0) {
        g_expsum[i] = 0.f;
        if (i == 0) g_loss = 0.f;
    }
    int t = i & (Tt-1);
    int ix = idx[i];
    int lb = lab[i];
    const float4* te = (const float4*)(tok_emb + (size_t)ix*Cc);
    const float4* le = (const float4*)(lab_emb + (size_t)lb*Cc);
    const float4* pe = (const float4*)(pos_emb + (size_t)t *Cc);
    float4* xo = (float4*)(g_x + (size_t)i*Cc);
    int c = threadIdx.x;
    float4 a = te[c], b = le[c], p = pe[c];
    xo[c] = make_float4(a.x+b.x+p.x, a.y+b.y+p.y, a.z+b.z+p.z, a.w+b.w+p.w);
}

// ---------------- layernorm: fp32 in -> fp16 hi/lo out ----------------
__global__ __launch_bounds__(128) void lnorm_k(const float* __restrict__ x,
                                               const float* __restrict__ g,
                                               const float* __restrict__ b,
                                               __half* __restrict__ yh,
                                               __half* __restrict__ yl) {
    int row = blockIdx.x;
    const float4* xr = (const float4*)(x + (size_t)row*Cc);
    float4 v = xr[threadIdx.x];
    float s  = v.x+v.y+v.z+v.w;
    float s2 = v.x*v.x + v.y*v.y + v.z*v.z + v.w*v.w;
    for (int o = 16; o > 0; o >>= 1) {
        s  += __shfl_down_sync(0xffffffff, s,  o);
        s2 += __shfl_down_sync(0xffffffff, s2, o);
    }
    __shared__ float sh[4], sh2[4];
    int wid = threadIdx.x >> 5, lane = threadIdx.x & 31;
    if (lane == 0) { sh[wid] = s; sh2[wid] = s2; }
    __syncthreads();
    __shared__ float smean, srstd;
    if (threadIdx.x == 0) {
        float ts = sh[0]+sh[1]+sh[2]+sh[3];
        float ts2 = sh2[0]+sh2[1]+sh2[2]+sh2[3];
        float mean = ts * (1.0f/Cc);
        float var = ts2 * (1.0f/Cc) - mean*mean;
        smean = mean;
        srstd = rsqrtf(var + 1e-5f);
    }
    __syncthreads();
    float mean = smean, rstd = srstd;
    int c = threadIdx.x * 4;
    float4 gg = *(const float4*)(g + c);
    float4 bb = *(const float4*)(b + c);
    float ov[4];
    ov[0] = (v.x-mean)*rstd*gg.x + bb.x;
    ov[1] = (v.y-mean)*rstd*gg.y + bb.y;
    ov[2] = (v.z-mean)*rstd*gg.z + bb.z;
    ov[3] = (v.w-mean)*rstd*gg.w + bb.w;
    __half hv[4], lv[4];
    #pragma unroll
    for (int e = 0; e < 4; e++) {
        hv[e] = __float2half_rn(ov[e]);
        lv[e] = __float2half_rn(ov[e] - __half2float(hv[e]));
    }
    *(uint2*)(yh + (size_t)row*Cc + c) = *(uint2*)hv;
    *(uint2*)(yl + (size_t)row*Cc + c) = *(uint2*)lv;
}

// ---------------- GEMM: fp16x3 on HMMA (BL=false -> fp16x2, no B-lo) ----------------
#define SAL_B 10240
#define SBH_B 20480
#define SBL_B 30720
#define STG_B 40960
#define TG_SMEM (2*STG_B)

template<bool BIAS, bool RELU, bool RES, bool SPLIT, bool EXPS, bool BL>
__global__ __launch_bounds__(256, 2) void tgemm_k(const __half* __restrict__ Ahg,
                                                  const __half* __restrict__ Alg,
                                                  const __half* __restrict__ Bhg,
                                                  const __half* __restrict__ Blg,
                                                  const float* __restrict__ bias,
                                                  const float* __restrict__ res,
                                                  float* __restrict__ Cf,
                                                  __half* __restrict__ Ch,
                                                  __half* __restrict__ Cl,
                                                  float* __restrict__ expsum,
                                                  int M, int N, int K) {
    extern __shared__ __half smd[];
    const int tid = threadIdx.x;
    const int lane = tid & 31, w = tid >> 5;
    const int row0 = blockIdx.y * 128, col0 = blockIdx.x * 128;
    const int m0w = (w >> 2) * 64, n0w = (w & 3) * 32;
    const u32 sb = (u32)__cvta_generic_to_shared(smd);

    float acc[4][4][4];
    #pragma unroll
    for (int i = 0; i < 4; i++)
        #pragma unroll
        for (int j = 0; j < 4; j++)
            #pragma unroll
            for (int e = 0; e < 4; e++) acc[i][j][e] = 0.f;

    const int nk = K >> 5;
    const int r = tid >> 1;
    const int hofs = (tid & 1) << 4;
    const __half* aHp = Ahg + (size_t)(row0 + r) * K + hofs;
    const __half* aLp = Alg + (size_t)(row0 + r) * K + hofs;
    const __half* bHp = Bhg + (size_t)(col0 + r) * K + hofs;
    const __half* bLp = BL ? (Blg + (size_t)(col0 + r) * K + hofs) : nullptr;
    const u32 dstA = sb + (u32)(r * 80 + hofs * 2);

    #define TG_ISSUE(bufbyte, kc) do {                                   \
        int _ko = (kc) << 5;                                             \
        u32 _d = dstA + (bufbyte);                                       \
        cpa16(_d,                 aHp + _ko);                            \
        cpa16(_d + 16,            aHp + _ko + 8);                        \
        cpa16(_d + SAL_B,         aLp + _ko);                            \
        cpa16(_d + SAL_B + 16,    aLp + _ko + 8);                        \
        cpa16(_d + SBH_B,         bHp + _ko);                            \
        cpa16(_d + SBH_B + 16,    bHp + _ko + 8);                        \
        if (BL) {                                                        \
            cpa16(_d + SBL_B,         bLp + _ko);                        \
            cpa16(_d + SBL_B + 16,    bLp + _ko + 8);                    \
        }                                                                \
    } while (0)

    TG_ISSUE(0, 0);
    cp_commit();

    const int lr = lane & 7, lg1 = (lane >> 3) & 1, lg2 = lane >> 4;

    for (int kt = 0; kt < nk; kt++) {
        const u32 cur = (u32)((kt & 1) * STG_B);
        cp_wait<0>();
        __syncthreads();
        if (kt + 1 < nk) {
            TG_ISSUE((u32)(((kt + 1) & 1) * STG_B), kt + 1);
            cp_commit();
        }

        #pragma unroll
        for (int ks = 0; ks < 32; ks += 16) {
            u32 afh[4][4], afl[4][4];
            #pragma unroll
            for (int mi = 0; mi < 4; mi++) {
                int row = m0w + mi*16 + lr + lg1*8;
                u32 ad = sb + cur + (u32)((row*40 + ks + lg2*8) * 2);
                ldsm4(afh[mi], ad);
                ldsm4(afl[mi], ad + SAL_B);
            }
            u32 bfh[4][2], bfl[4][2];
            #pragma unroll
            for (int bi = 0; bi < 2; bi++) {
                int n = n0w + bi*16 + lr + lg2*8;
                u32 bd = sb + cur + SBH_B + (u32)((n*40 + ks + lg1*8) * 2);
                u32 t1[4];
                ldsm4(t1, bd);
                bfh[2*bi][0]   = t1[0]; bfh[2*bi][1]   = t1[1];
                bfh[2*bi+1][0] = t1[2]; bfh[2*bi+1][1] = t1[3];
                if (BL) {
                    u32 t2[4];
                    ldsm4(t2, bd + (SBL_B - SBH_B));
                    bfl[2*bi][0]   = t2[0]; bfl[2*bi][1]   = t2[1];
                    bfl[2*bi+1][0] = t2[2]; bfl[2*bi+1][1] = t2[3];
                }
            }
            #pragma unroll
            for (int mi = 0; mi < 4; mi++)
                #pragma unroll
                for (int ni = 0; ni < 4; ni++) {
                    mma_f16(acc[mi][ni], afh[mi], bfh[ni]);
                    if (BL) mma_f16(acc[mi][ni], afh[mi], bfl[ni]);
                    mma_f16(acc[mi][ni], afl[mi], bfh[ni]);
                }
        }
    }
    #undef TG_ISSUE

    #pragma unroll
    for (int mi = 0; mi < 4; mi++) {
        int r0 = row0 + m0w + mi*16 + (lane >> 2);
        float es0 = 0.f, es1 = 0.f;
        #pragma unroll
        for (int ni = 0; ni < 4; ni++) {
            int cc = col0 + n0w + ni*8 + (lane & 3)*2;
            float2 v0 = make_float2(acc[mi][ni][0], acc[mi][ni][1]);
            float2 v1 = make_float2(acc[mi][ni][2], acc[mi][ni][3]);
            if (BIAS) {
                float2 bb = *(const float2*)(bias + cc);
                v0.x += bb.x; v0.y += bb.y; v1.x += bb.x; v1.y += bb.y;
            }
            if (RELU) {
                v0.x = fmaxf(v0.x, 0.f); v0.y = fmaxf(v0.y, 0.f);
                v1.x = fmaxf(v1.x, 0.f); v1.y = fmaxf(v1.y, 0.f);
            }
            if (RES) {
                float2 ra = *(const float2*)(res + (size_t)r0*N + cc);
                float2 rb = *(const float2*)(res + (size_t)(r0+8)*N + cc);
                v0.x += ra.x; v0.y += ra.y; v1.x += rb.x; v1.y += rb.y;
            }
            if (SPLIT) {
                __half h0 = __float2half_rn(v0.x), h1 = __float2half_rn(v0.y);
                __half h2 = __float2half_rn(v1.x), h3 = __float2half_rn(v1.y);
                __half l0 = __float2half_rn(v0.x - __half2float(h0));
                __half l1 = __float2half_rn(v0.y - __half2float(h1));
                __half l2 = __float2half_rn(v1.x - __half2float(h2));
                __half l3 = __float2half_rn(v1.y - __half2float(h3));
                *(__half2*)(Ch + (size_t)r0*N + cc)     = __halves2half2(h0, h1);
                *(__half2*)(Ch + (size_t)(r0+8)*N + cc) = __halves2half2(h2, h3);
                *(__half2*)(Cl + (size_t)r0*N + cc)     = __halves2half2(l0, l1);
                *(__half2*)(Cl + (size_t)(r0+8)*N + cc) = __halves2half2(l2, l3);
            } else {
                *(float2*)(Cf + (size_t)r0*N + cc) = v0;
                *(float2*)(Cf + (size_t)(r0+8)*N + cc) = v1;
            }
            if (EXPS) {
                es0 += __expf(v0.x) + __expf(v0.y);
                es1 += __expf(v1.x) + __expf(v1.y);
            }
        }
        if (EXPS) {
            es0 += __shfl_xor_sync(0xffffffffu, es0, 1);
            es0 += __shfl_xor_sync(0xffffffffu, es0, 2);
            es1 += __shfl_xor_sync(0xffffffffu, es1, 1);
            es1 += __shfl_xor_sync(0xffffffffu, es1, 2);
            if ((lane & 3) == 0) {
                atomicAdd(&expsum[r0], es0);
                atomicAdd(&expsum[r0 + 8], es1);
            }
        }
    }
}

// ---------------- tensor-core causal flash attention ----------------
#define AP 40
#define ASMEM (25600*2)

__global__ __launch_bounds__(128) void attn2_k(const __half* __restrict__ qkvh,
                                               const __half* __restrict__ qkvl,
                                               __half* __restrict__ ohg,
                                               __half* __restrict__ olg) {
    extern __shared__ __half ash[];
    const u32 sb = (u32)__cvta_generic_to_shared(ash);
    const int tid = threadIdx.x;
    const int l = tid & 31, w = tid >> 5;
    const int bh = blockIdx.y, b = bh >> 4, h = bh & 15;
    const int qt = (int)gridDim.x - 1 - (int)blockIdx.x;
    const float scale = 0.17677669529663689f;

    const int tb = b*Tt + qt*64;
    const int rr = tid >> 1;
    const int ss = tid & 1;

    {
        const __half* qh = qkvh + (size_t)(tb + rr)*NQKV + h*HSs + ss*16;
        const __half* ql = qkvl + (size_t)(tb + rr)*NQKV + h*HSs + ss*16;
        u32 d = sb + (u32)((rr*AP + ss*16) * 2);
        cpa16(d, qh);              cpa16(d + 16, qh + 8);
        cpa16(d + 2560*2, ql);     cpa16(d + 2560*2 + 16, ql + 8);
    }
    #define AT_ISSUE(stgh, kt) do {                                          \
        int _tok = b*Tt + (kt)*64 + rr;                                      \
        const __half* _kh = qkvh + (size_t)_tok*NQKV + 512  + h*HSs + ss*16; \
        const __half* _kl = qkvl + (size_t)_tok*NQKV + 512  + h*HSs + ss*16; \
        const __half* _vh = qkvh + (size_t)_tok*NQKV + 1024 + h*HSs + ss*16; \
        const __half* _vl = qkvl + (size_t)_tok*NQKV + 1024 + h*HSs + ss*16; \
        u32 _d = sb + (u32)(((stgh) + rr*AP + ss*16) * 2);                   \
        cpa16(_d, _kh);               cpa16(_d + 16, _kh + 8);               \
        cpa16(_d + 2560*2, _kl);      cpa16(_d + 2560*2 + 16, _kl + 8);      \
        cpa16(_d + 5120*2, _vh);      cpa16(_d + 5120*2 + 16, _vh + 8);      \
        cpa16(_d + 7680*2, _vl);      cpa16(_d + 7680*2 + 16, _vl + 8);      \
    } while (0)

    AT_ISSUE(5120, 0);
    cp_commit();

    const int lr = l & 7, lg1 = (l >> 3) & 1, lg2 = l >> 4;
    const int g = l >> 2;
    const int cq = (l & 3) * 2;

    u32 qah[2][4], qal[2][4];
    float m0 = -1e30f, m1 = -1e30f, sum0 = 0.f, sum1 = 0.f;
    float oacc[4][4];
    #pragma unroll
    for (int i = 0; i < 4; i++)
        #pragma unroll
        for (int e = 0; e < 4; e++) oacc[i][e] = 0.f;

    for (int kt = 0; kt <= qt; kt++) {
        const u32 stg = (u32)(5120 + (kt & 1) * 10240);
        cp_wait<0>();
        __syncthreads();
        if (kt < qt) { AT_ISSUE((u32)(5120 + ((kt+1) & 1) * 10240), kt + 1); cp_commit(); }
        if (kt == 0) {
            #pragma unroll
            for (int ks = 0; ks < 2; ks++) {
                int row = w*16 + lr + lg1*8;
                u32 ad = sb + (u32)((row*AP + ks*16 + lg2*8) * 2);
                ldsm4(qah[ks], ad);
                ldsm4(qal[ks], ad + 2560*2);
            }
        }

        float sc[8][4];
        #pragma unroll
        for (int nt = 0; nt < 8; nt++)
            #pragma unroll
            for (int e = 0; e < 4; e++) sc[nt][e] = 0.f;

        #pragma unroll
        for (int ks = 0; ks < 2; ks++) {
            u32 kbh[8][2], kbl[8][2];
            #pragma unroll
            for (int bi = 0; bi < 4; bi++) {
                int n = bi*16 + lr + lg2*8;
                u32 bd = sb + (u32)((stg + n*AP + ks*16 + lg1*8) * 2);
                u32 t1[4], t2[4];
                ldsm4(t1, bd);
                ldsm4(t2, bd + 2560*2);
                kbh[2*bi][0]   = t1[0]; kbh[2*bi][1]   = t1[1];
                kbh[2*bi+1][0] = t1[2]; kbh[2*bi+1][1] = t1[3];
                kbl[2*bi][0]   = t2[0]; kbl[2*bi][1]   = t2[1];
                kbl[2*bi+1][0] = t2[2]; kbl[2*bi+1][1] = t2[3];
            }
            #pragma unroll
            for (int nt = 0; nt < 8; nt++) {
                mma_f16(sc[nt], qah[ks], kbh[nt]);
                mma_f16(sc[nt], qah[ks], kbl[nt]);
                mma_f16(sc[nt], qal[ks], kbh[nt]);
            }
        }

        if (kt == qt) {
            int r0 = w*16 + g, r1 = r0 + 8;
            #pragma unroll
            for (int nt = 0; nt < 8; nt++) {
                int c0 = nt*8 + cq, c1 = c0 + 1;
                if (c0 > r0) sc[nt][0] = -1e30f;
                if (c1 > r0) sc[nt][1] = -1e30f;
                if (c0 > r1) sc[nt][2] = -1e30f;
                if (c1 > r1) sc[nt][3] = -1e30f;
            }
        }

        float t0 = -1e30f, t1 = -1e30f;
        #pragma unroll
        for (int nt = 0; nt < 8; nt++) {
            t0 = fmaxf(t0, fmaxf(sc[nt][0], sc[nt][1]));
            t1 = fmaxf(t1, fmaxf(sc[nt][2], sc[nt][3]));
        }
        t0 = fmaxf(t0, __shfl_xor_sync(0xffffffffu, t0, 1));
        t0 = fmaxf(t0, __shfl_xor_sync(0xffffffffu, t0, 2));
        t1 = fmaxf(t1, __shfl_xor_sync(0xffffffffu, t1, 1));
        t1 = fmaxf(t1, __shfl_xor_sync(0xffffffffu, t1, 2));
        float mn0 = fmaxf(m0, t0), mn1 = fmaxf(m1, t1);
        float cor0 = __expf((m0 - mn0) * scale);
        float cor1 = __expf((m1 - mn1) * scale);
        sum0 *= cor0; sum1 *= cor1;
        #pragma unroll
        for (int nt = 0; nt < 4; nt++) {
            oacc[nt][0] *= cor0; oacc[nt][1] *= cor0;
            oacc[nt][2] *= cor1; oacc[nt][3] *= cor1;
        }
        m0 = mn0; m1 = mn1;

        #pragma unroll
        for (int j = 0; j < 4; j++) {
            float p00 = __expf((sc[2*j][0]   - m0) * scale);
            float p01 = __expf((sc[2*j][1]   - m0) * scale);
            float p02 = __expf((sc[2*j][2]   - m1) * scale);
            float p03 = __expf((sc[2*j][3]   - m1) * scale);
            float p10 = __expf((sc[2*j+1][0] - m0) * scale);
            float p11 = __expf((sc[2*j+1][1] - m0) * scale);
            float p12 = __expf((sc[2*j+1][2] - m1) * scale);
            float p13 = __expf((sc[2*j+1][3] - m1) * scale);
            sum0 += p00 + p01 + p10 + p11;
            sum1 += p02 + p03 + p12 + p13;

            u32 pah[4], pal[4];
            pah[0] = packh2(p00, p01);
            pah[1] = packh2(p02, p03);
            pah[2] = packh2(p10, p11);
            pah[3] = packh2(p12, p13);
            {
                __half2* hp;
                hp = (__half2*)&pah[0];
                pal[0] = packh2(p00 - __half2float(__low2half(*hp)), p01 - __half2float(__high2half(*hp)));
                hp = (__half2*)&pah[1];
                pal[1] = packh2(p02 - __half2float(__low2half(*hp)), p03 - __half2float(__high2half(*hp)));
                hp = (__half2*)&pah[2];
                pal[2] = packh2(p10 - __half2float(__low2half(*hp)), p11 - __half2float(__high2half(*hp)));
                hp = (__half2*)&pah[3];
                pal[3] = packh2(p12 - __half2float(__low2half(*hp)), p13 - __half2float(__high2half(*hp)));
            }

            u32 vbh[4][2], vbl[4][2];
            #pragma unroll
            for (int vp = 0; vp < 2; vp++) {
                int krow = j*16 + (l & 7) + ((l >> 3) & 1) * 8;
                int ncol = vp*16 + (l >> 4) * 8;
                u32 vd = sb + (u32)((stg + 5120 + krow*AP + ncol) * 2);
                u32 t1r[4], t2r[4];
                ldsm4t(t1r, vd);
                ldsm4t(t2r, vd + 2560*2);
                vbh[2*vp][0]   = t1r[0]; vbh[2*vp][1]   = t1r[1];
                vbh[2*vp+1][0] = t1r[2]; vbh[2*vp+1][1] = t1r[3];
                vbl[2*vp][0]   = t2r[0]; vbl[2*vp][1]   = t2r[1];
                vbl[2*vp+1][0] = t2r[2]; vbl[2*vp+1][1] = t2r[3];
            }
            #pragma unroll
            for (int nt = 0; nt < 4; nt++) {
                mma_f16(oacc[nt], pah, vbh[nt]);
                mma_f16(oacc[nt], pah, vbl[nt]);
                mma_f16(oacc[nt], pal, vbh[nt]);
            }
        }
    }
    #undef AT_ISSUE

    sum0 += __shfl_xor_sync(0xffffffffu, sum0, 1);
    sum0 += __shfl_xor_sync(0xffffffffu, sum0, 2);
    sum1 += __shfl_xor_sync(0xffffffffu, sum1, 1);
    sum1 += __shfl_xor_sync(0xffffffffu, sum1, 2);
    float i0 = 1.f / sum0, i1 = 1.f / sum1;
    int tok0 = tb + w*16 + g;
    #pragma unroll
    for (int nt = 0; nt < 4; nt++) {
        int ch = h*HSs + nt*8 + cq;
        float v0 = oacc[nt][0]*i0, v1 = oacc[nt][1]*i0;
        float v2 = oacc[nt][2]*i1, v3 = oacc[nt][3]*i1;
        __half h0 = __float2half_rn(v0), h1 = __float2half_rn(v1);
        __half h2 = __float2half_rn(v2), h3 = __float2half_rn(v3);
        __half l0 = __float2half_rn(v0 - __half2float(h0));
        __half l1 = __float2half_rn(v1 - __half2float(h1));
        __half l2 = __float2half_rn(v2 - __half2float(h2));
        __half l3 = __float2half_rn(v3 - __half2float(h3));
        *(__half2*)(ohg + (size_t)tok0*Cc + ch)     = __halves2half2(h0, h1);
        *(__half2*)(ohg + (size_t)(tok0+8)*Cc + ch) = __halves2half2(h2, h3);
        *(__half2*)(olg + (size_t)tok0*Cc + ch)     = __halves2half2(l0, l1);
        *(__half2*)(olg + (size_t)(tok0+8)*Cc + ch) = __halves2half2(l2, l3);
    }
}

// ---------------- loss (fused path) ----------------
__global__ __launch_bounds__(256) void loss_final_k(const float* __restrict__ logits,
                                                    const int* __restrict__ targets) {
    int row = blockIdx.x * 256 + threadIdx.x;
    float lp = logits[(size_t)row * Vv + targets[row]] - logf(g_expsum[row]);
    for (int o = 16; o > 0; o >>= 1) lp += __shfl_down_sync(0xffffffff, lp, o);
    if ((threadIdx.x & 31) == 0) atomicAdd(&g_loss, lp);
}

__global__ void finalize_k(float* out, int extra) {
    float lv = -g_loss / (float)BT;
    for (int i = threadIdx.x + blockIdx.x*blockDim.x; i < extra; i += blockDim.x*gridDim.x)
        out[BTV + i] = lv;
}

// ---------------- host launcher ----------------
static void* symaddr(const void* sym) {
    void* p = nullptr;
    cudaGetSymbolAddress(&p, sym);
    return p;
}

extern "C" void kernel_launch(void* const* d_in, const int* in_sizes, int n_in,
                              void* d_out, int out_size) {
    const int*   idx      = (const int*)  d_in[0];
    const int*   idx_lab  = (const int*)  d_in[1];
    const int*   targets  = (const int*)  d_in[2];
    const float* tok_emb  = (const float*)d_in[3];
    const float* pos_emb  = (const float*)d_in[4];
    const float* lab_emb  = (const float*)d_in[5];
    const float* Wq       = (const float*)d_in[6];
    const float* Wk       = (const float*)d_in[7];
    const float* Wv       = (const float*)d_in[8];
    const float* Wo       = (const float*)d_in[9];
    const float* bo       = (const float*)d_in[10];
    const float* ln1_g    = (const float*)d_in[11];
    const float* ln1_b    = (const float*)d_in[12];
    const float* W1       = (const float*)d_in[13];
    const float* b1       = (const float*)d_in[14];
    const float* W2       = (const float*)d_in[15];
    const float* b2       = (const float*)d_in[16];
    const float* ln2_g    = (const float*)d_in[17];
    const float* ln2_b    = (const float*)d_in[18];
    const float* lnf_g    = (const float*)d_in[19];
    const float* lnf_b    = (const float*)d_in[20];
    const float* Wlm      = (const float*)d_in[21];
    const float* blm      = (const float*)d_in[22];
    float* out = (float*)d_out;

    float*  x    = (float*) symaddr(g_x);
    __half* qkvh = (__half*)symaddr(g_qkvh);
    __half* qkvl = (__half*)symaddr(g_qkvl);
    __half* hh   = (__half*)symaddr(g_hh);
    __half* hl   = (__half*)symaddr(g_hl);
    __half* oh   = (__half*)symaddr(g_oh);
    __half* ol   = (__half*)symaddr(g_ol);
    __half* ffh  = (__half*)symaddr(g_ffh);
    __half* ffl  = (__half*)symaddr(g_ffl);
    float*  esum = (float*) symaddr(g_expsum);
    __half* wqkv_h = (__half*)symaddr(g_wqkv_h);
    __half* wqkv_l = (__half*)symaddr(g_wqkv_l);
    __half* wo_h   = (__half*)symaddr(g_wo_h);
    __half* wo_l   = (__half*)symaddr(g_wo_l);
    __half* w1_h   = (__half*)symaddr(g_w1_h);
    __half* w1_l   = (__half*)symaddr(g_w1_l);
    __half* w2_h   = (__half*)symaddr(g_w2_h);
    __half* w2_l   = (__half*)symaddr(g_w2_l);
    __half* wlm_h  = (__half*)symaddr(g_wlm_h);
    __half* wlm_l  = (__half*)symaddr(g_wlm_l);

    cudaFuncSetAttribute(tgemm_k<false,false,false,true,false,true>,  cudaFuncAttributeMaxDynamicSharedMemorySize, TG_SMEM);
    cudaFuncSetAttribute(tgemm_k<true,false,true,false,false,true>,   cudaFuncAttributeMaxDynamicSharedMemorySize, TG_SMEM);
    cudaFuncSetAttribute(tgemm_k<true,true,false,true,false,true>,    cudaFuncAttributeMaxDynamicSharedMemorySize, TG_SMEM);
    cudaFuncSetAttribute(tgemm_k<false,false,false,true,false,false>, cudaFuncAttributeMaxDynamicSharedMemorySize, TG_SMEM);
    cudaFuncSetAttribute(tgemm_k<true,false,true,false,false,false>,  cudaFuncAttributeMaxDynamicSharedMemorySize, TG_SMEM);
    cudaFuncSetAttribute(tgemm_k<true,true,false,true,false,false>,   cudaFuncAttributeMaxDynamicSharedMemorySize, TG_SMEM);
    cudaFuncSetAttribute(tgemm_k<true,false,false,false,true,false>,  cudaFuncAttributeMaxDynamicSharedMemorySize, TG_SMEM);
    cudaFuncSetAttribute(attn2_k, cudaFuncAttributeMaxDynamicSharedMemorySize, ASMEM);

    prep_k<<<34816, dim3(32, 8)>>>(Wq, Wk, Wv, Wo, W1, W2, Wlm);
    embed_k<<<BT, 128>>>(idx, idx_lab, tok_emb, lab_emb, pos_emb);

    dim3 gQKV(NQKV/128, BT/128);   // (12, 64)
    dim3 g512(Cc/128,   BT/128);   // (4, 64)
    dim3 g2048(FFf/128, BT/128);   // (16, 64)
    dim3 gV(Vv/128,     BT/128);   // (64, 64)
    dim3 gattn(Tt/64, Bb*Hh);      // (16, 128)

    for (int l = 0; l < Ll; l++) {
        const bool x3 = (l < X2_LAYER);
        lnorm_k<<<BT, 128>>>(x, ln1_g + l*Cc, ln1_b + l*Cc, hh, hl);
        if (x3)
            tgemm_k<false,false,false,true,false,true><<<gQKV, 256, TG_SMEM>>>(
                hh, hl, wqkv_h + (size_t)l*NQKV*Cc, wqkv_l + (size_t)l*NQKV*Cc,
                nullptr, nullptr, nullptr, qkvh, qkvl, nullptr, BT, NQKV, Cc);
        else
            tgemm_k<false,false,false,true,false,false><<<gQKV, 256, TG_SMEM>>>(
                hh, hl, wqkv_h + (size_t)l*NQKV*Cc, wqkv_l + (size_t)l*NQKV*Cc,
                nullptr, nullptr, nullptr, qkvh, qkvl, nullptr, BT, NQKV, Cc);
        attn2_k<<<gattn, 128, ASMEM>>>(qkvh, qkvl, oh, ol);
        if (x3)
            tgemm_k<true,false,true,false,false,true><<<g512, 256, TG_SMEM>>>(
                oh, ol, wo_h + (size_t)l*Cc*Cc, wo_l + (size_t)l*Cc*Cc,
                bo + l*Cc, x, x, nullptr, nullptr, nullptr, BT, Cc, Cc);
        else
            tgemm_k<true,false,true,false,false,false><<<g512, 256, TG_SMEM>>>(
                oh, ol, wo_h + (size_t)l*Cc*Cc, wo_l + (size_t)l*Cc*Cc,
                bo + l*Cc, x, x, nullptr, nullptr, nullptr, BT, Cc, Cc);
        lnorm_k<<<BT, 128>>>(x, ln2_g + l*Cc, ln2_b + l*Cc, hh, hl);
        if (x3)
            tgemm_k<true,true,false,true,false,true><<<g2048, 256, TG_SMEM>>>(
                hh, hl, w1_h + (size_t)l*FFf*Cc, w1_l + (size_t)l*FFf*Cc,
                b1 + l*FFf, nullptr, nullptr, ffh, ffl, nullptr, BT, FFf, Cc);
        else
            tgemm_k<true,true,false,true,false,false><<<g2048, 256, TG_SMEM>>>(
                hh, hl, w1_h + (size_t)l*FFf*Cc, w1_l + (size_t)l*FFf*Cc,
                b1 + l*FFf, nullptr, nullptr, ffh, ffl, nullptr, BT, FFf, Cc);
        if (x3)
            tgemm_k<true,false,true,false,false,true><<<g512, 256, TG_SMEM>>>(
                ffh, ffl, w2_h + (size_t)l*Cc*FFf, w2_l + (size_t)l*Cc*FFf,
                b2 + l*Cc, x, x, nullptr, nullptr, nullptr, BT, Cc, FFf);
        else
            tgemm_k<true,false,true,false,false,false><<<g512, 256, TG_SMEM>>>(
                ffh, ffl, w2_h + (size_t)l*Cc*FFf, w2_l + (size_t)l*Cc*FFf,
                b2 + l*Cc, x, x, nullptr, nullptr, nullptr, BT, Cc, FFf);
    }
    lnorm_k<<<BT, 128>>>(x, lnf_g, lnf_b, hh, hl);
    // LM head: fp16x2 + fused expsum
    tgemm_k<true,false,false,false,true,false><<<gV, 256, TG_SMEM>>>(
        hh, hl, wlm_h, wlm_l, blm, nullptr, out, nullptr, nullptr, esum, BT, Vv, Cc);

    loss_final_k<<<BT/256, 256>>>(out, targets);
    int extra = out_size - (int)BTV;
    if (extra > 0) finalize_k<<<1, 128>>>(out, extra);
}